// round 9
// baseline (speedup 1.0000x reference)
#include <cuda_runtime.h>
#include <cstdint>
#include <math.h>
#include <mma.h>

using namespace nvcuda;

#define B_SZ   16384
#define NROWS  2048
#define NCOLS  128
#define CTRL   1024
#define NH     134            // NCOLS + 6
#define EPSV   1e-16f

// ---------------- scratch (device globals) ---------------------------------
__device__ float g_k[B_SZ * NCOLS];      // controller key k  [B,128]
__device__ float g_prm[B_SZ * 6];        // beta, g, s0,s1,s2, gamma
__device__ float g_mnorm[NROWS];         // ||M_j|| (exact)
__device__ float g_m32[NROWS * NCOLS];   // M rounded to tf32 (rna)

__device__ __forceinline__ float softplusf(float x) {
    return (x > 20.f) ? x : log1pf(expf(x));
}
__device__ __forceinline__ float fast_exp2f(float y) {
    y = fminf(fmaxf(y, -125.f), 126.f);
    float r = y + 12582912.f;
    int   n = __float_as_int(r) - 0x4B400000;
    float f = y - (r - 12582912.f);
    float p = 1.54035304e-4f;
    p = fmaf(p, f, 1.33335581e-3f);
    p = fmaf(p, f, 9.61812911e-3f);
    p = fmaf(p, f, 5.55041087e-2f);
    p = fmaf(p, f, 2.40226507e-1f);
    p = fmaf(p, f, 6.93147183e-1f);
    p = fmaf(p, f, 1.0f);
    return __int_as_float(__float_as_int(p) + (n << 23));
}
__device__ __forceinline__ float fast_expf(float x) { return fast_exp2f(x * 1.442695041f); }
__device__ __forceinline__ float fast_log2f(float x) {
    int   ib = __float_as_int(x);
    int   e  = (ib - 0x3f2aaaab) & 0xff800000;
    float m  = __int_as_float(ib - e);
    float le = (float)(e >> 23);
    float f  = m - 1.0f;
    float s  = f * f;
    float r  = fmaf(0.230836749f, f, -0.279208571f);
    float t  = fmaf(0.331826031f, f, -0.498910338f);
    r = fmaf(r, s, t);
    r = fmaf(r, s, f);
    return fmaf(r, 1.442695041f, le);
}
__device__ __forceinline__ float fast_powf(float x, float g) {
    return fast_exp2f(g * fast_log2f(x));
}

__device__ __forceinline__ float to_tf32f(float x) {
    uint32_t r; asm("cvt.rna.tf32.f32 %0, %1;" : "=r"(r) : "f"(x));
    return __uint_as_float(r);
}

typedef wmma::fragment<wmma::matrix_a, 16, 16, 8, wmma::precision::tf32, wmma::row_major> FragA;
typedef wmma::fragment<wmma::matrix_b, 16, 16, 8, wmma::precision::tf32, wmma::col_major> FragBC;
typedef wmma::fragment<wmma::matrix_b, 16, 16, 8, wmma::precision::tf32, wmma::row_major> FragBR;
typedef wmma::fragment<wmma::accumulator, 16, 16, 8, float> FragC;

// ---------------- K0: M row norms (exact) ----------------------------------
__global__ void k0_mnorm(const float* __restrict__ M) {
    int row  = blockIdx.x * 8 + (threadIdx.x >> 5);
    int lane = threadIdx.x & 31;
    const float4* M4 = (const float4*)(M + (size_t)row * NCOLS);
    float4 v = M4[lane];
    float s = v.x*v.x + v.y*v.y + v.z*v.z + v.w*v.w;
    #pragma unroll
    for (int o = 16; o > 0; o >>= 1) s += __shfl_xor_sync(0xffffffffu, s, o);
    if (lane == 0) g_mnorm[row] = sqrtf(s);
}
// ---------------- K0m: M -> tf32-rounded copy ------------------------------
__global__ void k0_mrnd(const float* __restrict__ M) {
    int idx = blockIdx.x * 256 + threadIdx.x;
    g_m32[idx] = to_tf32f(M[idx]);
}

// ---------------- K1: h = x@W + b (scalar fp32, R2-proven) -----------------
#define BM  128
#define BKK 32

__global__ __launch_bounds__(256)
void k1_gemm(const float* __restrict__ x, const float* __restrict__ W,
             const float* __restrict__ bfc) {
    __shared__ float As[BKK][132];
    __shared__ float Bs[BKK][128];
    __shared__ float Ps[BKK][6];
    __shared__ float hp[BM][6];

    int tid  = threadIdx.x;
    int row0 = blockIdx.x * BM;
    int tr   = tid >> 4;
    int tc   = tid & 15;
    int mp   = tid & 127;
    int cg   = tid >> 7;

    float acc[8][8];
    #pragma unroll
    for (int i = 0; i < 8; i++)
        #pragma unroll
        for (int j = 0; j < 8; j++) acc[i][j] = 0.f;
    float acc3[3] = {0.f, 0.f, 0.f};

    for (int kt = 0; kt < CTRL; kt += BKK) {
        #pragma unroll
        for (int u = 0; u < 4; u++) {
            int fid = tid + u * 256;
            int m = fid >> 3, kq = fid & 7;
            float4 v = *(const float4*)(x + (size_t)(row0 + m) * CTRL + kt + kq * 4);
            As[kq*4+0][m] = v.x; As[kq*4+1][m] = v.y;
            As[kq*4+2][m] = v.z; As[kq*4+3][m] = v.w;
        }
        #pragma unroll
        for (int u = 0; u < 16; u++) {
            int id = tid + u * 256;
            int k = id >> 7, n = id & 127;
            Bs[k][n] = W[(size_t)(kt + k) * NH + n];
        }
        if (tid < BKK * 6) {
            int k = tid / 6, c = tid % 6;
            Ps[k][c] = W[(size_t)(kt + k) * NH + 128 + c];
        }
        __syncthreads();

        #pragma unroll 4
        for (int kk = 0; kk < BKK; kk++) {
            float4 a0 = *(const float4*)&As[kk][tr*8];
            float4 a1 = *(const float4*)&As[kk][tr*8 + 4];
            float4 b0 = *(const float4*)&Bs[kk][tc*8];
            float4 b1 = *(const float4*)&Bs[kk][tc*8 + 4];
            float a[8] = {a0.x,a0.y,a0.z,a0.w,a1.x,a1.y,a1.z,a1.w};
            float b[8] = {b0.x,b0.y,b0.z,b0.w,b1.x,b1.y,b1.z,b1.w};
            #pragma unroll
            for (int i = 0; i < 8; i++)
                #pragma unroll
                for (int j = 0; j < 8; j++)
                    acc[i][j] = fmaf(a[i], b[j], acc[i][j]);
            float xv = As[kk][mp];
            #pragma unroll
            for (int c = 0; c < 3; c++)
                acc3[c] = fmaf(xv, Ps[kk][cg*3 + c], acc3[c]);
        }
        __syncthreads();
    }

    float bj[8];
    #pragma unroll
    for (int j = 0; j < 8; j++) bj[j] = bfc[tc*8 + j];
    #pragma unroll
    for (int i = 0; i < 8; i++) {
        int gr = row0 + tr*8 + i;
        float4 o0 = make_float4(acc[i][0]+bj[0], acc[i][1]+bj[1],
                                acc[i][2]+bj[2], acc[i][3]+bj[3]);
        float4 o1 = make_float4(acc[i][4]+bj[4], acc[i][5]+bj[5],
                                acc[i][6]+bj[6], acc[i][7]+bj[7]);
        *(float4*)(g_k + (size_t)gr * NCOLS + tc*8)     = o0;
        *(float4*)(g_k + (size_t)gr * NCOLS + tc*8 + 4) = o1;
    }

    #pragma unroll
    for (int c = 0; c < 3; c++)
        hp[mp][cg*3 + c] = acc3[c] + bfc[128 + cg*3 + c];
    __syncthreads();
    if (tid < BM) {
        float h0 = hp[tid][0], h1 = hp[tid][1], h2 = hp[tid][2];
        float h3 = hp[tid][3], h4 = hp[tid][4], h5 = hp[tid][5];
        float beta  = softplusf(h0);
        float g     = 1.f / (1.f + expf(-h1));
        float m3    = fmaxf(h2, fmaxf(h3, h4));
        float e0 = expf(h2 - m3), e1 = expf(h3 - m3), e2 = expf(h4 - m3);
        float inv = 1.f / (e0 + e1 + e2);
        float gamma = 1.f + softplusf(h5);
        size_t gr = (size_t)(row0 + tid) * 6;
        g_prm[gr+0] = beta;  g_prm[gr+1] = g;
        g_prm[gr+2] = e0*inv; g_prm[gr+3] = e1*inv; g_prm[gr+4] = e2*inv;
        g_prm[gr+5] = gamma;
    }
}

// ---------------- K2: fused addressing + read (wmma GEMM phases) -----------
#define RPB 16
#define K2T 512
#define SCRL 136      // scratch row stride (floats), mult of 8, 16B-aligned
// smem floats: wbuf 16*2048 | ks 16*128 | scr 2*16*136 | prm 16*8 | kn 16 | ips 16
#define K2_SMEM_FLOATS (RPB*NROWS + RPB*NCOLS + 2*RPB*SCRL + RPB*8 + RPB + RPB)
#define K2_SMEM_BYTES  (K2_SMEM_FLOATS * 4)

__global__ __launch_bounds__(K2T)
void k2_fused(const float* __restrict__ wprev, float* __restrict__ out) {
    extern __shared__ float smf[];
    float* wbuf = smf;                         // [16][2048]
    float* ks   = wbuf + RPB*NROWS;            // [16][128]
    float* scr  = ks + RPB*NCOLS;              // [2][16][136]
    float* prm  = scr + 2*RPB*SCRL;            // [16][8]
    float* kn   = prm + RPB*8;                 // [16]
    float* ips  = kn + RPB;                    // [16]

    int tid  = threadIdx.x;
    int lane = tid & 31;
    int wid  = tid >> 5;                       // 0..15
    int row0 = blockIdx.x * RPB;

    // load k rows + params (exact)
    {
        int r = tid >> 5;
        float4 v = *(const float4*)(g_k + (size_t)(row0 + r) * NCOLS + lane*4);
        *(float4*)&ks[r*NCOLS + lane*4] = v;
    }
    if (tid < RPB*6) {
        int r = tid / 6, c = tid % 6;
        prm[r*8 + c] = g_prm[(size_t)(row0 + r) * 6 + c];
    }
    __syncthreads();

    // k norms (exact, before rounding)
    {
        float s = 0.f;
        #pragma unroll
        for (int u = 0; u < 4; u++) {
            float v = ks[wid*NCOLS + lane + 32*u];
            s += v * v;
        }
        #pragma unroll
        for (int o = 16; o > 0; o >>= 1) s += __shfl_xor_sync(0xffffffffu, s, o);
        if (lane == 0) kn[wid] = sqrtf(s);
    }
    __syncthreads();

    // round ks to tf32 in place
    for (int i = tid; i < RPB*NCOLS; i += K2T) ks[i] = to_tf32f(ks[i]);
    __syncthreads();

    // ---- sim GEMM (wmma): wbuf[r][j] = dot(k_r, M_j) ----
    {
        #pragma unroll
        for (int i = 0; i < 8; i++) {
            int j0 = (i * 16 + wid) * 16;
            FragC acc;
            wmma::fill_fragment(acc, 0.0f);
            #pragma unroll
            for (int kk = 0; kk < 16; kk++) {
                FragA a;
                FragBC b;
                wmma::load_matrix_sync(a, ks + kk*8, NCOLS);
                wmma::load_matrix_sync(b, g_m32 + (size_t)j0 * NCOLS + kk*8, NCOLS);
                wmma::mma_sync(acc, a, b, acc);
            }
            wmma::store_matrix_sync(wbuf + j0, acc, NROWS, wmma::mem_row_major);
        }
    }
    __syncthreads();

    // scale logits: beta * dot / (||k||*||M|| + EPS)
    for (int idx = tid; idx < RPB*NROWS; idx += K2T) {
        int r = idx >> 11, j = idx & (NROWS-1);
        wbuf[idx] = prm[r*8 + 0] * wbuf[idx] / (kn[r] * g_mnorm[j] + EPSV);
    }
    __syncthreads();

    // ---- per-warp row pipeline (R2-proven): softmax -> blend -> shift -> pow
    {
        int r = wid;
        float* wr = wbuf + r*NROWS;
        float g  = prm[r*8+1], s0 = prm[r*8+2], s1 = prm[r*8+3];
        float s2 = prm[r*8+4], gm = prm[r*8+5];

        float mx = -1e30f;
        for (int u = 0; u < 64; u++) mx = fmaxf(mx, wr[lane + 32*u]);
        #pragma unroll
        for (int o = 16; o > 0; o >>= 1) mx = fmaxf(mx, __shfl_xor_sync(0xffffffffu, mx, o));

        float sum = 0.f;
        for (int u = 0; u < 64; u++) {
            int idx = lane + 32*u;
            float e = fast_expf(wr[idx] - mx);
            wr[idx] = e;
            sum += e;
        }
        #pragma unroll
        for (int o = 16; o > 0; o >>= 1) sum += __shfl_xor_sync(0xffffffffu, sum, o);

        float gc = g / sum, og = 1.f - g;
        const float* wp = wprev + (size_t)(row0 + r) * NROWS;
        for (int u = 0; u < 64; u++) {
            int idx = lane + 32*u;
            wr[idx] = gc * wr[idx] + og * __ldg(wp + idx);
        }
        __syncwarp();

        float w0    = wr[0];
        float carry = wr[NROWS - 1];
        float psum  = 0.f;
        for (int ch = 0; ch < 64; ch++) {
            int j = ch*32 + lane;
            float c0  = wr[j];
            float lft = (lane == 0)      ? carry : wr[j-1];
            float rgt = (j == NROWS - 1) ? w0    : wr[j+1];
            float t = s0*lft + s1*c0 + s2*rgt + EPSV;
            float p = fast_powf(t, gm);
            __syncwarp();
            wr[j] = p;
            carry = __shfl_sync(0xffffffffu, c0, 31);
            psum += p;
            __syncwarp();
        }
        #pragma unroll
        for (int o = 16; o > 0; o >>= 1) psum += __shfl_xor_sync(0xffffffffu, psum, o);
        if (lane == 0) ips[r] = 1.f / psum;
    }
    __syncthreads();

    // round w (unnormalized) to tf32 in place
    for (int i = tid; i < RPB*NROWS; i += K2T) wbuf[i] = to_tf32f(wbuf[i]);
    __syncthreads();

    // ---- read GEMM (wmma): out_blk = w @ M, split-K halves ----
    {
        int n0 = (wid & 7) * 16;
        int kh = wid >> 3;
        FragC acc;
        wmma::fill_fragment(acc, 0.0f);
        for (int kk = 0; kk < 128; kk++) {
            int kg = kh * 1024 + kk * 8;
            FragA a;
            FragBR b;
            wmma::load_matrix_sync(a, wbuf + kg, NROWS);
            wmma::load_matrix_sync(b, g_m32 + (size_t)kg * NCOLS + n0, NCOLS);
            wmma::mma_sync(acc, a, b, acc);
        }
        wmma::store_matrix_sync(scr + kh * RPB * SCRL + n0, acc, SCRL,
                                wmma::mem_row_major);
    }
    __syncthreads();
    #pragma unroll
    for (int u = 0; u < 4; u++) {
        int idx = tid + u * K2T;
        int r = idx >> 7, c = idx & 127;
        float v = scr[r*SCRL + c] + scr[RPB*SCRL + r*SCRL + c];
        out[(size_t)(row0 + r) * NCOLS + c] = v * ips[r];
    }
}

// ---------------- launch ----------------------------------------------------
extern "C" void kernel_launch(void* const* d_in, const int* in_sizes, int n_in,
                              void* d_out, int out_size) {
    const float *x = 0, *W = 0, *b = 0, *M = 0, *wprev = 0;
    for (int i = 0; i < n_in; i++) {
        switch (in_sizes[i]) {
            case B_SZ * CTRL:   x     = (const float*)d_in[i]; break;
            case CTRL * NH:     W     = (const float*)d_in[i]; break;
            case NH:            b     = (const float*)d_in[i]; break;
            case NROWS * NCOLS: M     = (const float*)d_in[i]; break;
            case B_SZ * NROWS:  wprev = (const float*)d_in[i]; break;
        }
    }
    float* out = (float*)d_out;

    cudaFuncSetAttribute(k2_fused, cudaFuncAttributeMaxDynamicSharedMemorySize,
                         K2_SMEM_BYTES);

    k0_mnorm<<<NROWS/8, 256>>>(M);
    k0_mrnd <<<(NROWS*NCOLS)/256, 256>>>(M);
    k1_gemm <<<B_SZ/BM, 256>>>(x, W, b);
    k2_fused<<<B_SZ/RPB, K2T, K2_SMEM_BYTES>>>(wprev, out);
}

// round 10
// speedup vs baseline: 1.0066x; 1.0066x over previous
#include <cuda_runtime.h>
#include <cstdint>
#include <math.h>
#include <mma.h>

using namespace nvcuda;

#define B_SZ   16384
#define NROWS  2048
#define NCOLS  128
#define CTRL   1024
#define NH     134            // NCOLS + 6
#define EPSV   1e-16f

// ---------------- scratch (device globals) ---------------------------------
__device__ float g_k[B_SZ * NCOLS];      // controller key k  [B,128]
__device__ float g_prm[B_SZ * 6];        // beta, g, s0,s1,s2, gamma
__device__ float g_mnorm[NROWS];         // ||M_j|| (exact)
__device__ float g_m32[NROWS * NCOLS];   // M rounded to tf32 (rna)

__device__ __forceinline__ float softplusf(float x) {
    return (x > 20.f) ? x : log1pf(expf(x));
}
__device__ __forceinline__ float fast_exp2f(float y) {
    y = fminf(fmaxf(y, -125.f), 126.f);
    float r = y + 12582912.f;
    int   n = __float_as_int(r) - 0x4B400000;
    float f = y - (r - 12582912.f);
    float p = 1.54035304e-4f;
    p = fmaf(p, f, 1.33335581e-3f);
    p = fmaf(p, f, 9.61812911e-3f);
    p = fmaf(p, f, 5.55041087e-2f);
    p = fmaf(p, f, 2.40226507e-1f);
    p = fmaf(p, f, 6.93147183e-1f);
    p = fmaf(p, f, 1.0f);
    return __int_as_float(__float_as_int(p) + (n << 23));
}
__device__ __forceinline__ float fast_expf(float x) { return fast_exp2f(x * 1.442695041f); }
__device__ __forceinline__ float fast_log2f(float x) {
    int   ib = __float_as_int(x);
    int   e  = (ib - 0x3f2aaaab) & 0xff800000;
    float m  = __int_as_float(ib - e);
    float le = (float)(e >> 23);
    float f  = m - 1.0f;
    float s  = f * f;
    float r  = fmaf(0.230836749f, f, -0.279208571f);
    float t  = fmaf(0.331826031f, f, -0.498910338f);
    r = fmaf(r, s, t);
    r = fmaf(r, s, f);
    return fmaf(r, 1.442695041f, le);
}
__device__ __forceinline__ float fast_powf(float x, float g) {
    return fast_exp2f(g * fast_log2f(x));
}
__device__ __forceinline__ float to_tf32f(float x) {
    uint32_t r; asm("cvt.rna.tf32.f32 %0, %1;" : "=r"(r) : "f"(x));
    return __uint_as_float(r);
}

typedef wmma::fragment<wmma::matrix_a, 16, 16, 8, wmma::precision::tf32, wmma::row_major> FragA;
typedef wmma::fragment<wmma::matrix_b, 16, 16, 8, wmma::precision::tf32, wmma::col_major> FragBC;
typedef wmma::fragment<wmma::matrix_b, 16, 16, 8, wmma::precision::tf32, wmma::row_major> FragBR;
typedef wmma::fragment<wmma::accumulator, 16, 16, 8, float> FragC;

// ---------------- K0: M row norms (exact) + tf32 copy ----------------------
__global__ void k0_mnorm(const float* __restrict__ M) {
    int row  = blockIdx.x * 8 + (threadIdx.x >> 5);
    int lane = threadIdx.x & 31;
    float4 v = ((const float4*)(M + (size_t)row * NCOLS))[lane];
    float s = v.x*v.x + v.y*v.y + v.z*v.z + v.w*v.w;
    #pragma unroll
    for (int o = 16; o > 0; o >>= 1) s += __shfl_xor_sync(0xffffffffu, s, o);
    if (lane == 0) g_mnorm[row] = sqrtf(s);
}
__global__ void k0_mrnd(const float* __restrict__ M) {
    int idx = blockIdx.x * 256 + threadIdx.x;
    g_m32[idx] = to_tf32f(M[idx]);
}

// ---------------- K1: h = x@W + b (wmma GEMM + exact params) ---------------
// dynamic smem layout (bytes):
//   [0, 67584)   union: { As[32][132] exact | As32[128][36] | Bs32[128][36] }
//                 overlapped later by stage[128][132]
//   [67584, +768)  Ps[32][6]
//   [68352, +3072) hp[128][6]
#define K1_AS    0
#define K1_AS32  16896
#define K1_BS32  35328
#define K1_PS    67584
#define K1_HP    68352
#define K1_SMEM  71424

__global__ __launch_bounds__(256)
void k1_gemm(const float* __restrict__ x, const float* __restrict__ W,
             const float* __restrict__ bfc) {
    extern __shared__ char sm1[];
    float* As    = (float*)(sm1 + K1_AS);     // [32][132] exact, k-major
    float* As32  = (float*)(sm1 + K1_AS32);   // [128][36] tf32, m-major
    float* Bs32  = (float*)(sm1 + K1_BS32);   // [128][36] tf32, n-major
    float* stage = (float*)sm1;               // [128][132] post-mainloop
    float* Ps    = (float*)(sm1 + K1_PS);     // [32][6]
    float* hp    = (float*)(sm1 + K1_HP);     // [128][6]

    int tid  = threadIdx.x;
    int wid  = tid >> 5;
    int wm   = wid >> 2, wn = wid & 3;
    int row0 = blockIdx.x * 128;
    int mp   = tid & 127;
    int cg   = tid >> 7;

    FragC acc[4][2];
    #pragma unroll
    for (int mi = 0; mi < 4; mi++)
        #pragma unroll
        for (int ni = 0; ni < 2; ni++) wmma::fill_fragment(acc[mi][ni], 0.0f);
    float acc3[3] = {0.f, 0.f, 0.f};

    for (int kt = 0; kt < CTRL / 32; kt++) {
        // x tile: exact to As[k][m], rounded to As32[m][k]
        #pragma unroll
        for (int u = 0; u < 4; u++) {
            int idx = tid + u * 256;
            int m = idx >> 3, c4 = idx & 7;
            float4 v = *(const float4*)(x + (size_t)(row0 + m) * CTRL + kt * 32 + c4 * 4);
            As[(c4*4+0)*132 + m] = v.x; As[(c4*4+1)*132 + m] = v.y;
            As[(c4*4+2)*132 + m] = v.z; As[(c4*4+3)*132 + m] = v.w;
            float* d = As32 + m * 36 + c4 * 4;
            d[0] = to_tf32f(v.x); d[1] = to_tf32f(v.y);
            d[2] = to_tf32f(v.z); d[3] = to_tf32f(v.w);
        }
        // W tile -> Bs32[n][k] (rounded)
        #pragma unroll
        for (int u = 0; u < 16; u++) {
            int id = tid + u * 256;
            int k = id >> 7, n = id & 127;
            Bs32[n * 36 + k] = to_tf32f(W[(size_t)(kt*32 + k) * NH + n]);
        }
        if (tid < 32 * 6) {
            int k = tid / 6, c = tid % 6;
            Ps[k*6 + c] = W[(size_t)(kt*32 + k) * NH + 128 + c];
        }
        __syncthreads();

        // wmma mainloop
        #pragma unroll
        for (int ks = 0; ks < 4; ks++) {
            int k0 = ks * 8;
            FragA a[4];
            #pragma unroll
            for (int mi = 0; mi < 4; mi++)
                wmma::load_matrix_sync(a[mi], As32 + (wm*64 + mi*16) * 36 + k0, 36);
            #pragma unroll
            for (int ni = 0; ni < 2; ni++) {
                FragBC b;
                wmma::load_matrix_sync(b, Bs32 + (wn*32 + ni*16) * 36 + k0, 36);
                #pragma unroll
                for (int mi = 0; mi < 4; mi++)
                    wmma::mma_sync(acc[mi][ni], a[mi], b, acc[mi][ni]);
            }
        }
        // exact param accumulation (thread mp handles row mp)
        #pragma unroll 8
        for (int kk = 0; kk < 32; kk++) {
            float xv = As[kk*132 + mp];
            #pragma unroll
            for (int c = 0; c < 3; c++)
                acc3[c] = fmaf(xv, Ps[kk*6 + cg*3 + c], acc3[c]);
        }
        __syncthreads();
    }

    // stage accumulators (overlaps As/As32/Bs32 — all consumers done)
    #pragma unroll
    for (int mi = 0; mi < 4; mi++)
        #pragma unroll
        for (int ni = 0; ni < 2; ni++)
            wmma::store_matrix_sync(stage + (wm*64 + mi*16) * 132 + wn*32 + ni*16,
                                    acc[mi][ni], 132, wmma::mem_row_major);
    #pragma unroll
    for (int c = 0; c < 3; c++)
        hp[mp*6 + cg*3 + c] = acc3[c] + bfc[128 + cg*3 + c];
    __syncthreads();

    // k epilogue: +bias, store
    {
        int c4 = tid & 31;
        float4 bj = *(const float4*)(bfc + c4 * 4);
        #pragma unroll
        for (int u = 0; u < 4; u++) {
            int idx = tid + u * 256;
            int row = idx >> 5;
            float4 v = *(float4*)&stage[row * 132 + c4 * 4];
            v.x += bj.x; v.y += bj.y; v.z += bj.z; v.w += bj.w;
            *(float4*)(g_k + (size_t)(row0 + row) * NCOLS + c4 * 4) = v;
        }
    }
    // param activations (proven)
    if (tid < 128) {
        float h0 = hp[tid*6+0], h1 = hp[tid*6+1], h2 = hp[tid*6+2];
        float h3 = hp[tid*6+3], h4 = hp[tid*6+4], h5 = hp[tid*6+5];
        float beta  = softplusf(h0);
        float g     = 1.f / (1.f + expf(-h1));
        float m3    = fmaxf(h2, fmaxf(h3, h4));
        float e0 = expf(h2 - m3), e1 = expf(h3 - m3), e2 = expf(h4 - m3);
        float inv = 1.f / (e0 + e1 + e2);
        float gamma = 1.f + softplusf(h5);
        size_t gr = (size_t)(row0 + tid) * 6;
        g_prm[gr+0] = beta;  g_prm[gr+1] = g;
        g_prm[gr+2] = e0*inv; g_prm[gr+3] = e1*inv; g_prm[gr+4] = e2*inv;
        g_prm[gr+5] = gamma;
    }
}

// ---------------- K2: fused addressing + read (conflict-free wmma) ---------
#define RPB  16
#define K2T  512
#define WSTR 2056     // wbuf row stride (mod 32 banks = 8; 16B multiple)
#define KSTR 136      // ks row stride
#define SCRL 136
// smem floats: wbuf 16*2056 | ks 16*136 | scr 2*16*136 | prm 128 | kn 16 | ips 16
#define K2_SMEM_FLOATS (RPB*WSTR + RPB*KSTR + 2*RPB*SCRL + RPB*8 + RPB + RPB)
#define K2_SMEM_BYTES  (K2_SMEM_FLOATS * 4)

__global__ __launch_bounds__(K2T)
void k2_fused(const float* __restrict__ wprev, float* __restrict__ out) {
    extern __shared__ float smf[];
    float* wbuf = smf;                         // [16][2056]
    float* ks   = wbuf + RPB*WSTR;             // [16][136]
    float* scr  = ks + RPB*KSTR;               // [2][16][136]
    float* prm  = scr + 2*RPB*SCRL;            // [16][8]
    float* kn   = prm + RPB*8;                 // [16]
    float* ips  = kn + RPB;                    // [16]

    int tid  = threadIdx.x;
    int lane = tid & 31;
    int wid  = tid >> 5;                       // 0..15
    int row0 = blockIdx.x * RPB;

    // load k rows + params (exact)
    {
        int r = tid >> 5;
        float4 v = *(const float4*)(g_k + (size_t)(row0 + r) * NCOLS + lane*4);
        *(float4*)&ks[r*KSTR + lane*4] = v;
    }
    if (tid < RPB*6) {
        int r = tid / 6, c = tid % 6;
        prm[r*8 + c] = g_prm[(size_t)(row0 + r) * 6 + c];
    }
    __syncthreads();

    // k norms (exact, before rounding)
    {
        float s = 0.f;
        #pragma unroll
        for (int u = 0; u < 4; u++) {
            float v = ks[wid*KSTR + lane + 32*u];
            s += v * v;
        }
        #pragma unroll
        for (int o = 16; o > 0; o >>= 1) s += __shfl_xor_sync(0xffffffffu, s, o);
        if (lane == 0) kn[wid] = sqrtf(s);
    }
    __syncthreads();

    // round ks to tf32 in place
    for (int i = tid; i < RPB*NCOLS; i += K2T) {
        int r = i >> 7, c = i & 127;
        ks[r*KSTR + c] = to_tf32f(ks[r*KSTR + c]);
    }
    __syncthreads();

    // ---- sim GEMM (wmma, A hoisted): wbuf[r][j] = dot(k_r, M_j) ----
    {
        FragC acc[8];
        #pragma unroll
        for (int i = 0; i < 8; i++) wmma::fill_fragment(acc[i], 0.0f);
        #pragma unroll
        for (int kk = 0; kk < 16; kk++) {
            FragA a;
            wmma::load_matrix_sync(a, ks + kk*8, KSTR);
            #pragma unroll
            for (int i = 0; i < 8; i++) {
                int j0 = (i * 16 + wid) * 16;
                FragBC b;
                wmma::load_matrix_sync(b, g_m32 + (size_t)j0 * NCOLS + kk*8, NCOLS);
                wmma::mma_sync(acc[i], a, b, acc[i]);
            }
        }
        #pragma unroll
        for (int i = 0; i < 8; i++) {
            int j0 = (i * 16 + wid) * 16;
            wmma::store_matrix_sync(wbuf + j0, acc[i], WSTR, wmma::mem_row_major);
        }
    }
    __syncthreads();

    // scale logits: beta * dot / (||k||*||M|| + EPS)
    for (int i = tid; i < RPB*NROWS; i += K2T) {
        int r = i >> 11, j = i & (NROWS-1);
        wbuf[r*WSTR + j] = prm[r*8 + 0] * wbuf[r*WSTR + j] / (kn[r] * g_mnorm[j] + EPSV);
    }
    __syncthreads();

    // ---- per-warp row pipeline (proven): softmax -> blend -> shift -> pow
    {
        int r = wid;
        float* wr = wbuf + r*WSTR;
        float g  = prm[r*8+1], s0 = prm[r*8+2], s1 = prm[r*8+3];
        float s2 = prm[r*8+4], gm = prm[r*8+5];

        float mx = -1e30f;
        for (int u = 0; u < 64; u++) mx = fmaxf(mx, wr[lane + 32*u]);
        #pragma unroll
        for (int o = 16; o > 0; o >>= 1) mx = fmaxf(mx, __shfl_xor_sync(0xffffffffu, mx, o));

        float sum = 0.f;
        for (int u = 0; u < 64; u++) {
            int idx = lane + 32*u;
            float e = fast_expf(wr[idx] - mx);
            wr[idx] = e;
            sum += e;
        }
        #pragma unroll
        for (int o = 16; o > 0; o >>= 1) sum += __shfl_xor_sync(0xffffffffu, sum, o);

        float gc = g / sum, og = 1.f - g;
        const float* wp = wprev + (size_t)(row0 + r) * NROWS;
        for (int u = 0; u < 64; u++) {
            int idx = lane + 32*u;
            wr[idx] = gc * wr[idx] + og * __ldg(wp + idx);
        }
        __syncwarp();

        float w0    = wr[0];
        float carry = wr[NROWS - 1];
        float psum  = 0.f;
        for (int ch = 0; ch < 64; ch++) {
            int j = ch*32 + lane;
            float c0  = wr[j];
            float lft = (lane == 0)      ? carry : wr[j-1];
            float rgt = (j == NROWS - 1) ? w0    : wr[j+1];
            float t = s0*lft + s1*c0 + s2*rgt + EPSV;
            float p = fast_powf(t, gm);
            __syncwarp();
            wr[j] = p;
            carry = __shfl_sync(0xffffffffu, c0, 31);
            psum += p;
            __syncwarp();
        }
        #pragma unroll
        for (int o = 16; o > 0; o >>= 1) psum += __shfl_xor_sync(0xffffffffu, psum, o);
        if (lane == 0) ips[r] = 1.f / psum;
    }
    __syncthreads();

    // round w (unnormalized) to tf32 in place
    for (int i = tid; i < RPB*NROWS; i += K2T) {
        int r = i >> 11, j = i & (NROWS-1);
        wbuf[r*WSTR + j] = to_tf32f(wbuf[r*WSTR + j]);
    }
    __syncthreads();

    // ---- read GEMM (wmma): out_blk = w @ M, split-K halves ----
    {
        int n0 = (wid & 7) * 16;
        int kh = wid >> 3;
        FragC acc;
        wmma::fill_fragment(acc, 0.0f);
        for (int kk = 0; kk < 128; kk++) {
            int kg = kh * 1024 + kk * 8;
            FragA a;
            FragBR b;
            wmma::load_matrix_sync(a, wbuf + kg, WSTR);
            wmma::load_matrix_sync(b, g_m32 + (size_t)kg * NCOLS + n0, NCOLS);
            wmma::mma_sync(acc, a, b, acc);
        }
        wmma::store_matrix_sync(scr + kh * RPB * SCRL + n0, acc, SCRL,
                                wmma::mem_row_major);
    }
    __syncthreads();
    #pragma unroll
    for (int u = 0; u < 4; u++) {
        int idx = tid + u * K2T;
        int r = idx >> 7, c = idx & 127;
        float v = scr[r*SCRL + c] + scr[RPB*SCRL + r*SCRL + c];
        out[(size_t)(row0 + r) * NCOLS + c] = v * ips[r];
    }
}

// ---------------- launch ----------------------------------------------------
extern "C" void kernel_launch(void* const* d_in, const int* in_sizes, int n_in,
                              void* d_out, int out_size) {
    const float *x = 0, *W = 0, *b = 0, *M = 0, *wprev = 0;
    for (int i = 0; i < n_in; i++) {
        switch (in_sizes[i]) {
            case B_SZ * CTRL:   x     = (const float*)d_in[i]; break;
            case CTRL * NH:     W     = (const float*)d_in[i]; break;
            case NH:            b     = (const float*)d_in[i]; break;
            case NROWS * NCOLS: M     = (const float*)d_in[i]; break;
            case B_SZ * NROWS:  wprev = (const float*)d_in[i]; break;
        }
    }
    float* out = (float*)d_out;

    cudaFuncSetAttribute(k1_gemm, cudaFuncAttributeMaxDynamicSharedMemorySize, K1_SMEM);
    cudaFuncSetAttribute(k2_fused, cudaFuncAttributeMaxDynamicSharedMemorySize,
                         K2_SMEM_BYTES);

    k0_mnorm<<<NROWS/8, 256>>>(M);
    k0_mrnd <<<(NROWS*NCOLS)/256, 256>>>(M);
    k1_gemm <<<B_SZ/128, 256, K1_SMEM>>>(x, W, b);
    k2_fused<<<B_SZ/RPB, K2T, K2_SMEM_BYTES>>>(wprev, out);
}

// round 13
// speedup vs baseline: 1.5393x; 1.5293x over previous
#include <cuda_runtime.h>
#include <cstdint>
#include <math.h>
#include <mma.h>

using namespace nvcuda;

#define B_SZ   16384
#define NROWS  2048
#define NCOLS  128
#define CTRL   1024
#define NH     134            // NCOLS + 6
#define EPSV   1e-16f

// ---------------- scratch (device globals) ---------------------------------
__device__ float g_k[B_SZ * NCOLS];      // controller key k  [B,128]
__device__ float g_prm[B_SZ * 6];        // beta, g, s0,s1,s2, gamma
__device__ float g_mnorm[NROWS];         // ||M_j|| (exact)
__device__ float g_m32[NROWS * NCOLS];   // M rounded to tf32 (rna)

__device__ __forceinline__ float softplusf(float x) {
    return (x > 20.f) ? x : log1pf(expf(x));
}
__device__ __forceinline__ float fast_exp2f(float y) {
    y = fminf(fmaxf(y, -125.f), 126.f);
    float r = y + 12582912.f;
    int   n = __float_as_int(r) - 0x4B400000;
    float f = y - (r - 12582912.f);
    float p = 1.54035304e-4f;
    p = fmaf(p, f, 1.33335581e-3f);
    p = fmaf(p, f, 9.61812911e-3f);
    p = fmaf(p, f, 5.55041087e-2f);
    p = fmaf(p, f, 2.40226507e-1f);
    p = fmaf(p, f, 6.93147183e-1f);
    p = fmaf(p, f, 1.0f);
    return __int_as_float(__float_as_int(p) + (n << 23));
}
__device__ __forceinline__ float fast_expf(float x) { return fast_exp2f(x * 1.442695041f); }
__device__ __forceinline__ float fast_log2f(float x) {
    int   ib = __float_as_int(x);
    int   e  = (ib - 0x3f2aaaab) & 0xff800000;
    float m  = __int_as_float(ib - e);
    float le = (float)(e >> 23);
    float f  = m - 1.0f;
    float s  = f * f;
    float r  = fmaf(0.230836749f, f, -0.279208571f);
    float t  = fmaf(0.331826031f, f, -0.498910338f);
    r = fmaf(r, s, t);
    r = fmaf(r, s, f);
    return fmaf(r, 1.442695041f, le);
}
__device__ __forceinline__ float fast_powf(float x, float g) {
    return fast_exp2f(g * fast_log2f(x));
}
__device__ __forceinline__ float to_tf32f(float x) {
    uint32_t r; asm("cvt.rna.tf32.f32 %0, %1;" : "=r"(r) : "f"(x));
    return __uint_as_float(r);
}

typedef wmma::fragment<wmma::matrix_a, 16, 16, 8, wmma::precision::tf32, wmma::row_major> FragA;
typedef wmma::fragment<wmma::matrix_b, 16, 16, 8, wmma::precision::tf32, wmma::col_major> FragBC;
typedef wmma::fragment<wmma::matrix_b, 16, 16, 8, wmma::precision::tf32, wmma::row_major> FragBR;
typedef wmma::fragment<wmma::accumulator, 16, 16, 8, float> FragC;

// ---------------- K0: M row norms (exact) + tf32 copy ----------------------
__global__ void k0_mnorm(const float* __restrict__ M) {
    int row  = blockIdx.x * 8 + (threadIdx.x >> 5);
    int lane = threadIdx.x & 31;
    float4 v = ((const float4*)(M + (size_t)row * NCOLS))[lane];
    float s = v.x*v.x + v.y*v.y + v.z*v.z + v.w*v.w;
    #pragma unroll
    for (int o = 16; o > 0; o >>= 1) s += __shfl_xor_sync(0xffffffffu, s, o);
    if (lane == 0) g_mnorm[row] = sqrtf(s);
}
__global__ void k0_mrnd(const float* __restrict__ M) {
    int idx = blockIdx.x * 256 + threadIdx.x;
    g_m32[idx] = to_tf32f(M[idx]);
}

// ---------------- K1: h = x@W + b (wmma GEMM + exact params) — R10-proven --
#define K1_AS    0
#define K1_AS32  16896
#define K1_BS32  35328
#define K1_PS    67584
#define K1_HP    68352
#define K1_SMEM  71424

__global__ __launch_bounds__(256)
void k1_gemm(const float* __restrict__ x, const float* __restrict__ W,
             const float* __restrict__ bfc) {
    extern __shared__ char sm1[];
    float* As    = (float*)(sm1 + K1_AS);
    float* As32  = (float*)(sm1 + K1_AS32);
    float* Bs32  = (float*)(sm1 + K1_BS32);
    float* stage = (float*)sm1;
    float* Ps    = (float*)(sm1 + K1_PS);
    float* hp    = (float*)(sm1 + K1_HP);

    int tid  = threadIdx.x;
    int wid  = tid >> 5;
    int wm   = wid >> 2, wn = wid & 3;
    int row0 = blockIdx.x * 128;
    int mp   = tid & 127;
    int cg   = tid >> 7;

    FragC acc[4][2];
    #pragma unroll
    for (int mi = 0; mi < 4; mi++)
        #pragma unroll
        for (int ni = 0; ni < 2; ni++) wmma::fill_fragment(acc[mi][ni], 0.0f);
    float acc3[3] = {0.f, 0.f, 0.f};

    for (int kt = 0; kt < CTRL / 32; kt++) {
        #pragma unroll
        for (int u = 0; u < 4; u++) {
            int idx = tid + u * 256;
            int m = idx >> 3, c4 = idx & 7;
            float4 v = *(const float4*)(x + (size_t)(row0 + m) * CTRL + kt * 32 + c4 * 4);
            As[(c4*4+0)*132 + m] = v.x; As[(c4*4+1)*132 + m] = v.y;
            As[(c4*4+2)*132 + m] = v.z; As[(c4*4+3)*132 + m] = v.w;
            float* d = As32 + m * 36 + c4 * 4;
            d[0] = to_tf32f(v.x); d[1] = to_tf32f(v.y);
            d[2] = to_tf32f(v.z); d[3] = to_tf32f(v.w);
        }
        #pragma unroll
        for (int u = 0; u < 16; u++) {
            int id = tid + u * 256;
            int k = id >> 7, n = id & 127;
            Bs32[n * 36 + k] = to_tf32f(W[(size_t)(kt*32 + k) * NH + n]);
        }
        if (tid < 32 * 6) {
            int k = tid / 6, c = tid % 6;
            Ps[k*6 + c] = W[(size_t)(kt*32 + k) * NH + 128 + c];
        }
        __syncthreads();

        #pragma unroll
        for (int ks = 0; ks < 4; ks++) {
            int k0 = ks * 8;
            FragA a[4];
            #pragma unroll
            for (int mi = 0; mi < 4; mi++)
                wmma::load_matrix_sync(a[mi], As32 + (wm*64 + mi*16) * 36 + k0, 36);
            #pragma unroll
            for (int ni = 0; ni < 2; ni++) {
                FragBC b;
                wmma::load_matrix_sync(b, Bs32 + (wn*32 + ni*16) * 36 + k0, 36);
                #pragma unroll
                for (int mi = 0; mi < 4; mi++)
                    wmma::mma_sync(acc[mi][ni], a[mi], b, acc[mi][ni]);
            }
        }
        #pragma unroll 8
        for (int kk = 0; kk < 32; kk++) {
            float xv = As[kk*132 + mp];
            #pragma unroll
            for (int c = 0; c < 3; c++)
                acc3[c] = fmaf(xv, Ps[kk*6 + cg*3 + c], acc3[c]);
        }
        __syncthreads();
    }

    #pragma unroll
    for (int mi = 0; mi < 4; mi++)
        #pragma unroll
        for (int ni = 0; ni < 2; ni++)
            wmma::store_matrix_sync(stage + (wm*64 + mi*16) * 132 + wn*32 + ni*16,
                                    acc[mi][ni], 132, wmma::mem_row_major);
    #pragma unroll
    for (int c = 0; c < 3; c++)
        hp[mp*6 + cg*3 + c] = acc3[c] + bfc[128 + cg*3 + c];
    __syncthreads();

    {
        int c4 = tid & 31;
        float4 bj = *(const float4*)(bfc + c4 * 4);
        #pragma unroll
        for (int u = 0; u < 4; u++) {
            int idx = tid + u * 256;
            int row = idx >> 5;
            float4 v = *(float4*)&stage[row * 132 + c4 * 4];
            v.x += bj.x; v.y += bj.y; v.z += bj.z; v.w += bj.w;
            *(float4*)(g_k + (size_t)(row0 + row) * NCOLS + c4 * 4) = v;
        }
    }
    if (tid < 128) {
        float h0 = hp[tid*6+0], h1 = hp[tid*6+1], h2 = hp[tid*6+2];
        float h3 = hp[tid*6+3], h4 = hp[tid*6+4], h5 = hp[tid*6+5];
        float beta  = softplusf(h0);
        float g     = 1.f / (1.f + expf(-h1));
        float m3    = fmaxf(h2, fmaxf(h3, h4));
        float e0 = expf(h2 - m3), e1 = expf(h3 - m3), e2 = expf(h4 - m3);
        float inv = 1.f / (e0 + e1 + e2);
        float gamma = 1.f + softplusf(h5);
        size_t gr = (size_t)(row0 + tid) * 6;
        g_prm[gr+0] = beta;  g_prm[gr+1] = g;
        g_prm[gr+2] = e0*inv; g_prm[gr+3] = e1*inv; g_prm[gr+4] = e2*inv;
        g_prm[gr+5] = gamma;
    }
}

// ---------------- K2: fused addressing + read, 1024 threads ----------------
#define RPB  16
#define K2T  1024
#define WSTR 2056     // wbuf row stride
#define KSTR 136      // ks row stride
#define SCRL 136
#define NKQ  4        // read-GEMM K quarters
// smem floats: wbuf 16*2056 | ks 16*136 | scr 4*16*136 | prm 128 | kn 16 | ips 16
#define K2_SMEM_FLOATS (RPB*WSTR + RPB*KSTR + NKQ*RPB*SCRL + RPB*8 + RPB + RPB)
#define K2_SMEM_BYTES  (K2_SMEM_FLOATS * 4)

__global__ __launch_bounds__(K2T)
void k2_fused(const float* __restrict__ wprev, float* __restrict__ out) {
    extern __shared__ float smf[];
    float* wbuf = smf;                         // [16][2056]
    float* ks   = wbuf + RPB*WSTR;             // [16][136]
    float* scr  = ks + RPB*KSTR;               // [4][16][136]
    float* prm  = scr + NKQ*RPB*SCRL;          // [16][8]
    float* kn   = prm + RPB*8;                 // [16]
    float* ips  = kn + RPB;                    // [16]

    int tid  = threadIdx.x;
    int lane = tid & 31;
    int wid  = tid >> 5;                       // 0..31
    int row0 = blockIdx.x * RPB;

    // load k rows (threads 0..511) + params (exact)
    if (tid < 512) {
        int r = tid >> 5;
        float4 v = *(const float4*)(g_k + (size_t)(row0 + r) * NCOLS + lane*4);
        *(float4*)&ks[r*KSTR + lane*4] = v;
    }
    if (tid < RPB*6) {
        int r = tid / 6, c = tid % 6;
        prm[r*8 + c] = g_prm[(size_t)(row0 + r) * 6 + c];
    }
    __syncthreads();

    // k norms (exact, before rounding): warps 0..15
    if (wid < 16) {
        float s = 0.f;
        #pragma unroll
        for (int u = 0; u < 4; u++) {
            float v = ks[wid*KSTR + lane + 32*u];
            s += v * v;
        }
        #pragma unroll
        for (int o = 16; o > 0; o >>= 1) s += __shfl_xor_sync(0xffffffffu, s, o);
        if (lane == 0) kn[wid] = sqrtf(s);
    }
    __syncthreads();

    // round ks to tf32 in place
    for (int i = tid; i < RPB*NCOLS; i += K2T) {
        int r = i >> 7, c = i & 127;
        ks[r*KSTR + c] = to_tf32f(ks[r*KSTR + c]);
    }
    __syncthreads();

    // ---- sim GEMM (wmma, A hoisted): 32 warps x 4 j-tiles -----------------
    {
        FragC acc[4];
        #pragma unroll
        for (int i = 0; i < 4; i++) wmma::fill_fragment(acc[i], 0.0f);
        #pragma unroll
        for (int kk = 0; kk < 16; kk++) {
            FragA a;
            wmma::load_matrix_sync(a, ks + kk*8, KSTR);
            #pragma unroll
            for (int i = 0; i < 4; i++) {
                int j0 = (wid * 4 + i) * 16;
                FragBC b;
                wmma::load_matrix_sync(b, g_m32 + (size_t)j0 * NCOLS + kk*8, NCOLS);
                wmma::mma_sync(acc[i], a, b, acc[i]);
            }
        }
        #pragma unroll
        for (int i = 0; i < 4; i++) {
            int j0 = (wid * 4 + i) * 16;
            wmma::store_matrix_sync(wbuf + j0, acc[i], WSTR, wmma::mem_row_major);
        }
    }
    __syncthreads();

    // scale logits: beta * dot / (||k||*||M|| + EPS)
    for (int i = tid; i < RPB*NROWS; i += K2T) {
        int r = i >> 11, j = i & (NROWS-1);
        wbuf[r*WSTR + j] = prm[r*8 + 0] * wbuf[r*WSTR + j] / (kn[r] * g_mnorm[j] + EPSV);
    }
    __syncthreads();

    // ---- per-warp row pipeline (proven, warps 0..15): softmax->blend->shift->pow
    if (wid < 16) {
        int r = wid;
        float* wr = wbuf + r*WSTR;
        float g  = prm[r*8+1], s0 = prm[r*8+2], s1 = prm[r*8+3];
        float s2 = prm[r*8+4], gm = prm[r*8+5];

        float mx = -1e30f;
        for (int u = 0; u < 64; u++) mx = fmaxf(mx, wr[lane + 32*u]);
        #pragma unroll
        for (int o = 16; o > 0; o >>= 1) mx = fmaxf(mx, __shfl_xor_sync(0xffffffffu, mx, o));

        float sum = 0.f;
        for (int u = 0; u < 64; u++) {
            int idx = lane + 32*u;
            float e = fast_expf(wr[idx] - mx);
            wr[idx] = e;
            sum += e;
        }
        #pragma unroll
        for (int o = 16; o > 0; o >>= 1) sum += __shfl_xor_sync(0xffffffffu, sum, o);

        float gc = g / sum, og = 1.f - g;
        const float* wp = wprev + (size_t)(row0 + r) * NROWS;
        for (int u = 0; u < 64; u++) {
            int idx = lane + 32*u;
            wr[idx] = gc * wr[idx] + og * __ldg(wp + idx);
        }
        __syncwarp();

        float w0    = wr[0];
        float carry = wr[NROWS - 1];
        float psum  = 0.f;
        for (int ch = 0; ch < 64; ch++) {
            int j = ch*32 + lane;
            float c0  = wr[j];
            float lft = (lane == 0)      ? carry : wr[j-1];
            float rgt = (j == NROWS - 1) ? w0    : wr[j+1];
            float t = s0*lft + s1*c0 + s2*rgt + EPSV;
            float p = fast_powf(t, gm);
            __syncwarp();
            wr[j] = p;
            carry = __shfl_sync(0xffffffffu, c0, 31);
            psum += p;
            __syncwarp();
        }
        #pragma unroll
        for (int o = 16; o > 0; o >>= 1) psum += __shfl_xor_sync(0xffffffffu, psum, o);
        if (lane == 0) ips[r] = 1.f / psum;
    }
    __syncthreads();

    // round w (unnormalized) to tf32 in place
    for (int i = tid; i < RPB*NROWS; i += K2T) {
        int r = i >> 11, j = i & (NROWS-1);
        wbuf[r*WSTR + j] = to_tf32f(wbuf[r*WSTR + j]);
    }
    __syncthreads();

    // ---- read GEMM (wmma): out_blk = w @ M, 8 n-tiles x 4 K-quarters ------
    {
        int n0 = (wid & 7) * 16;
        int kq = wid >> 3;                     // 0..3
        FragC acc;
        wmma::fill_fragment(acc, 0.0f);
        for (int kk = 0; kk < 64; kk++) {
            int kg = kq * 512 + kk * 8;
            FragA a;
            FragBR b;
            wmma::load_matrix_sync(a, wbuf + kg, WSTR);
            wmma::load_matrix_sync(b, g_m32 + (size_t)kg * NCOLS + n0, NCOLS);
            wmma::mma_sync(acc, a, b, acc);
        }
        wmma::store_matrix_sync(scr + kq * RPB * SCRL + n0, acc, SCRL,
                                wmma::mem_row_major);
    }
    __syncthreads();
    #pragma unroll
    for (int u = 0; u < 2; u++) {
        int idx = tid + u * K2T;
        int r = idx >> 7, c = idx & 127;
        float v = scr[r*SCRL + c] + scr[RPB*SCRL + r*SCRL + c]
                + scr[2*RPB*SCRL + r*SCRL + c] + scr[3*RPB*SCRL + r*SCRL + c];
        out[(size_t)(row0 + r) * NCOLS + c] = v * ips[r];
    }
}

// ---------------- launch ----------------------------------------------------
extern "C" void kernel_launch(void* const* d_in, const int* in_sizes, int n_in,
                              void* d_out, int out_size) {
    const float *x = 0, *W = 0, *b = 0, *M = 0, *wprev = 0;
    for (int i = 0; i < n_in; i++) {
        switch (in_sizes[i]) {
            case B_SZ * CTRL:   x     = (const float*)d_in[i]; break;
            case CTRL * NH:     W     = (const float*)d_in[i]; break;
            case NH:            b     = (const float*)d_in[i]; break;
            case NROWS * NCOLS: M     = (const float*)d_in[i]; break;
            case B_SZ * NROWS:  wprev = (const float*)d_in[i]; break;
        }
    }
    float* out = (float*)d_out;

    cudaFuncSetAttribute(k1_gemm, cudaFuncAttributeMaxDynamicSharedMemorySize, K1_SMEM);
    cudaFuncSetAttribute(k2_fused, cudaFuncAttributeMaxDynamicSharedMemorySize,
                         K2_SMEM_BYTES);

    k0_mnorm<<<NROWS/8, 256>>>(M);
    k0_mrnd <<<(NROWS*NCOLS)/256, 256>>>(M);
    k1_gemm <<<B_SZ/128, 256, K1_SMEM>>>(x, W, b);
    k2_fused<<<B_SZ/RPB, K2T, K2_SMEM_BYTES>>>(wprev, out);
}

// round 14
// speedup vs baseline: 1.5533x; 1.0091x over previous
#include <cuda_runtime.h>
#include <cstdint>
#include <math.h>
#include <mma.h>

using namespace nvcuda;

#define B_SZ   16384
#define NROWS  2048
#define NCOLS  128
#define CTRL   1024
#define NH     134            // NCOLS + 6
#define EPSV   1e-16f

// ---------------- scratch (device globals) ---------------------------------
__device__ float g_k[B_SZ * NCOLS];      // controller key k  [B,128]
__device__ float g_prm[B_SZ * 6];        // beta, g, s0,s1,s2, gamma
__device__ float g_mnorm[NROWS];         // ||M_j|| (exact)
__device__ float g_m32[NROWS * NCOLS];   // M rounded to tf32 (rna)

__device__ __forceinline__ float softplusf(float x) {
    return (x > 20.f) ? x : log1pf(expf(x));
}
__device__ __forceinline__ float fast_exp2f(float y) {
    y = fminf(fmaxf(y, -125.f), 126.f);
    float r = y + 12582912.f;
    int   n = __float_as_int(r) - 0x4B400000;
    float f = y - (r - 12582912.f);
    float p = 1.54035304e-4f;
    p = fmaf(p, f, 1.33335581e-3f);
    p = fmaf(p, f, 9.61812911e-3f);
    p = fmaf(p, f, 5.55041087e-2f);
    p = fmaf(p, f, 2.40226507e-1f);
    p = fmaf(p, f, 6.93147183e-1f);
    p = fmaf(p, f, 1.0f);
    return __int_as_float(__float_as_int(p) + (n << 23));
}
__device__ __forceinline__ float fast_expf(float x) { return fast_exp2f(x * 1.442695041f); }
__device__ __forceinline__ float fast_log2f(float x) {
    int   ib = __float_as_int(x);
    int   e  = (ib - 0x3f2aaaab) & 0xff800000;
    float m  = __int_as_float(ib - e);
    float le = (float)(e >> 23);
    float f  = m - 1.0f;
    float s  = f * f;
    float r  = fmaf(0.230836749f, f, -0.279208571f);
    float t  = fmaf(0.331826031f, f, -0.498910338f);
    r = fmaf(r, s, t);
    r = fmaf(r, s, f);
    return fmaf(r, 1.442695041f, le);
}
__device__ __forceinline__ float fast_powf(float x, float g) {
    return fast_exp2f(g * fast_log2f(x));
}
__device__ __forceinline__ float to_tf32f(float x) {
    uint32_t r; asm("cvt.rna.tf32.f32 %0, %1;" : "=r"(r) : "f"(x));
    return __uint_as_float(r);
}

typedef wmma::fragment<wmma::matrix_a, 16, 16, 8, wmma::precision::tf32, wmma::row_major> FragA;
typedef wmma::fragment<wmma::matrix_b, 16, 16, 8, wmma::precision::tf32, wmma::col_major> FragBC;
typedef wmma::fragment<wmma::matrix_b, 16, 16, 8, wmma::precision::tf32, wmma::row_major> FragBR;
typedef wmma::fragment<wmma::accumulator, 16, 16, 8, float> FragC;

// ---------------- K0: M row norms (exact) + tf32 copy ----------------------
__global__ void k0_mnorm(const float* __restrict__ M) {
    int row  = blockIdx.x * 8 + (threadIdx.x >> 5);
    int lane = threadIdx.x & 31;
    float4 v = ((const float4*)(M + (size_t)row * NCOLS))[lane];
    float s = v.x*v.x + v.y*v.y + v.z*v.z + v.w*v.w;
    #pragma unroll
    for (int o = 16; o > 0; o >>= 1) s += __shfl_xor_sync(0xffffffffu, s, o);
    if (lane == 0) g_mnorm[row] = sqrtf(s);
}
__global__ void k0_mrnd(const float* __restrict__ M) {
    int idx = blockIdx.x * 256 + threadIdx.x;
    g_m32[idx] = to_tf32f(M[idx]);
}

// ---------------- K1: h = x@W + b (wmma GEMM + exact params, prefetched) ---
#define K1_AS    0
#define K1_AS32  16896
#define K1_BS32  35328
#define K1_PS    67584
#define K1_HP    68352
#define K1_SMEM  71424

__global__ __launch_bounds__(256)
void k1_gemm(const float* __restrict__ x, const float* __restrict__ W,
             const float* __restrict__ bfc) {
    extern __shared__ char sm1[];
    float* As    = (float*)(sm1 + K1_AS);
    float* As32  = (float*)(sm1 + K1_AS32);
    float* Bs32  = (float*)(sm1 + K1_BS32);
    float* stage = (float*)sm1;
    float* Ps    = (float*)(sm1 + K1_PS);
    float* hp    = (float*)(sm1 + K1_HP);

    int tid  = threadIdx.x;
    int wid  = tid >> 5;
    int wm   = wid >> 2, wn = wid & 3;
    int row0 = blockIdx.x * 128;
    int mp   = tid & 127;
    int cg   = tid >> 7;

    FragC acc[4][2];
    #pragma unroll
    for (int mi = 0; mi < 4; mi++)
        #pragma unroll
        for (int ni = 0; ni < 2; ni++) wmma::fill_fragment(acc[mi][ni], 0.0f);
    float acc3[3] = {0.f, 0.f, 0.f};

    // prefetch registers
    float4 xv[4];
    float  wv[16];
    float  pvv = 0.f;
    int xm[4], xc[4];
    #pragma unroll
    for (int u = 0; u < 4; u++) {
        int idx = tid + u * 256;
        xm[u] = idx >> 3; xc[u] = idx & 7;
    }

    // prefetch tile 0
    #pragma unroll
    for (int u = 0; u < 4; u++)
        xv[u] = *(const float4*)(x + (size_t)(row0 + xm[u]) * CTRL + xc[u] * 4);
    #pragma unroll
    for (int u = 0; u < 16; u++) {
        int id = tid + u * 256;
        int k = id >> 7, n = id & 127;
        wv[u] = W[(size_t)k * NH + n];
    }
    if (tid < 32 * 6)
        pvv = W[(size_t)(tid / 6) * NH + 128 + (tid % 6)];

    for (int kt = 0; kt < CTRL / 32; kt++) {
        // store prefetched tile to smem
        #pragma unroll
        for (int u = 0; u < 4; u++) {
            int m = xm[u], c4 = xc[u];
            float4 v = xv[u];
            As[(c4*4+0)*132 + m] = v.x; As[(c4*4+1)*132 + m] = v.y;
            As[(c4*4+2)*132 + m] = v.z; As[(c4*4+3)*132 + m] = v.w;
            float* d = As32 + m * 36 + c4 * 4;
            d[0] = to_tf32f(v.x); d[1] = to_tf32f(v.y);
            d[2] = to_tf32f(v.z); d[3] = to_tf32f(v.w);
        }
        #pragma unroll
        for (int u = 0; u < 16; u++) {
            int id = tid + u * 256;
            int k = id >> 7, n = id & 127;
            Bs32[n * 36 + k] = to_tf32f(wv[u]);
        }
        if (tid < 32 * 6)
            Ps[(tid / 6) * 6 + (tid % 6)] = pvv;
        __syncthreads();

        // prefetch next tile (overlaps MMA below)
        if (kt + 1 < CTRL / 32) {
            int kb = (kt + 1) * 32;
            #pragma unroll
            for (int u = 0; u < 4; u++)
                xv[u] = *(const float4*)(x + (size_t)(row0 + xm[u]) * CTRL + kb + xc[u] * 4);
            #pragma unroll
            for (int u = 0; u < 16; u++) {
                int id = tid + u * 256;
                int k = id >> 7, n = id & 127;
                wv[u] = W[(size_t)(kb + k) * NH + n];
            }
            if (tid < 32 * 6)
                pvv = W[(size_t)(kb + tid / 6) * NH + 128 + (tid % 6)];
        }

        #pragma unroll
        for (int ks = 0; ks < 4; ks++) {
            int k0 = ks * 8;
            FragA a[4];
            #pragma unroll
            for (int mi = 0; mi < 4; mi++)
                wmma::load_matrix_sync(a[mi], As32 + (wm*64 + mi*16) * 36 + k0, 36);
            #pragma unroll
            for (int ni = 0; ni < 2; ni++) {
                FragBC b;
                wmma::load_matrix_sync(b, Bs32 + (wn*32 + ni*16) * 36 + k0, 36);
                #pragma unroll
                for (int mi = 0; mi < 4; mi++)
                    wmma::mma_sync(acc[mi][ni], a[mi], b, acc[mi][ni]);
            }
        }
        #pragma unroll 8
        for (int kk = 0; kk < 32; kk++) {
            float xvv = As[kk*132 + mp];
            #pragma unroll
            for (int c = 0; c < 3; c++)
                acc3[c] = fmaf(xvv, Ps[kk*6 + cg*3 + c], acc3[c]);
        }
        __syncthreads();
    }

    #pragma unroll
    for (int mi = 0; mi < 4; mi++)
        #pragma unroll
        for (int ni = 0; ni < 2; ni++)
            wmma::store_matrix_sync(stage + (wm*64 + mi*16) * 132 + wn*32 + ni*16,
                                    acc[mi][ni], 132, wmma::mem_row_major);
    #pragma unroll
    for (int c = 0; c < 3; c++)
        hp[mp*6 + cg*3 + c] = acc3[c] + bfc[128 + cg*3 + c];
    __syncthreads();

    {
        int c4 = tid & 31;
        float4 bj = *(const float4*)(bfc + c4 * 4);
        #pragma unroll
        for (int u = 0; u < 4; u++) {
            int idx = tid + u * 256;
            int row = idx >> 5;
            float4 v = *(float4*)&stage[row * 132 + c4 * 4];
            v.x += bj.x; v.y += bj.y; v.z += bj.z; v.w += bj.w;
            *(float4*)(g_k + (size_t)(row0 + row) * NCOLS + c4 * 4) = v;
        }
    }
    if (tid < 128) {
        float h0 = hp[tid*6+0], h1 = hp[tid*6+1], h2 = hp[tid*6+2];
        float h3 = hp[tid*6+3], h4 = hp[tid*6+4], h5 = hp[tid*6+5];
        float beta  = softplusf(h0);
        float g     = 1.f / (1.f + expf(-h1));
        float m3    = fmaxf(h2, fmaxf(h3, h4));
        float e0 = expf(h2 - m3), e1 = expf(h3 - m3), e2 = expf(h4 - m3);
        float inv = 1.f / (e0 + e1 + e2);
        float gamma = 1.f + softplusf(h5);
        size_t gr = (size_t)(row0 + tid) * 6;
        g_prm[gr+0] = beta;  g_prm[gr+1] = g;
        g_prm[gr+2] = e0*inv; g_prm[gr+3] = e1*inv; g_prm[gr+4] = e2*inv;
        g_prm[gr+5] = gamma;
    }
}

// ---------------- K2: fused addressing + read, 1024 threads ----------------
#define RPB  16
#define K2T  1024
#define WSTR 2056     // wbuf row stride
#define KSTR 136      // ks row stride
#define SCRL 136
#define NKQ  4        // read-GEMM K quarters
#define HALF 1024     // pointwise elements per warp (2 warps per row)
// smem floats: wbuf 16*2056 | ks 16*136 | scr 4*16*136 | prm 128 | kn 16 | ips 16 | red 32
#define K2_SMEM_FLOATS (RPB*WSTR + RPB*KSTR + NKQ*RPB*SCRL + RPB*8 + RPB + RPB + 32)
#define K2_SMEM_BYTES  (K2_SMEM_FLOATS * 4)

__global__ __launch_bounds__(K2T)
void k2_fused(const float* __restrict__ wprev, float* __restrict__ out) {
    extern __shared__ float smf[];
    float* wbuf = smf;                         // [16][2056]
    float* ks   = wbuf + RPB*WSTR;             // [16][136]
    float* scr  = ks + RPB*KSTR;               // [4][16][136]
    float* prm  = scr + NKQ*RPB*SCRL;          // [16][8]
    float* kn   = prm + RPB*8;                 // [16]
    float* ips  = kn + RPB;                    // [16]
    float* red  = ips + RPB;                   // [32] cross-warp partials

    int tid  = threadIdx.x;
    int lane = tid & 31;
    int wid  = tid >> 5;                       // 0..31
    int row0 = blockIdx.x * RPB;

    // load k rows (threads 0..511) + params (exact)
    if (tid < 512) {
        int r = tid >> 5;
        float4 v = *(const float4*)(g_k + (size_t)(row0 + r) * NCOLS + lane*4);
        *(float4*)&ks[r*KSTR + lane*4] = v;
    }
    if (tid < RPB*6) {
        int r = tid / 6, c = tid % 6;
        prm[r*8 + c] = g_prm[(size_t)(row0 + r) * 6 + c];
    }
    __syncthreads();

    // k norms (exact, before rounding): warps 0..15
    if (wid < 16) {
        float s = 0.f;
        #pragma unroll
        for (int u = 0; u < 4; u++) {
            float v = ks[wid*KSTR + lane + 32*u];
            s += v * v;
        }
        #pragma unroll
        for (int o = 16; o > 0; o >>= 1) s += __shfl_xor_sync(0xffffffffu, s, o);
        if (lane == 0) kn[wid] = sqrtf(s);
    }
    __syncthreads();

    // round ks to tf32 in place
    for (int i = tid; i < RPB*NCOLS; i += K2T) {
        int r = i >> 7, c = i & 127;
        ks[r*KSTR + c] = to_tf32f(ks[r*KSTR + c]);
    }
    __syncthreads();

    // ---- sim GEMM (wmma, A hoisted): 32 warps x 4 j-tiles -----------------
    {
        FragC acc[4];
        #pragma unroll
        for (int i = 0; i < 4; i++) wmma::fill_fragment(acc[i], 0.0f);
        #pragma unroll
        for (int kk = 0; kk < 16; kk++) {
            FragA a;
            wmma::load_matrix_sync(a, ks + kk*8, KSTR);
            #pragma unroll
            for (int i = 0; i < 4; i++) {
                int j0 = (wid * 4 + i) * 16;
                FragBC b;
                wmma::load_matrix_sync(b, g_m32 + (size_t)j0 * NCOLS + kk*8, NCOLS);
                wmma::mma_sync(acc[i], a, b, acc[i]);
            }
        }
        #pragma unroll
        for (int i = 0; i < 4; i++) {
            int j0 = (wid * 4 + i) * 16;
            wmma::store_matrix_sync(wbuf + j0, acc[i], WSTR, wmma::mem_row_major);
        }
    }
    __syncthreads();

    // scale logits: beta * dot / (||k||*||M|| + EPS)
    for (int i = tid; i < RPB*NROWS; i += K2T) {
        int r = i >> 11, j = i & (NROWS-1);
        wbuf[r*WSTR + j] = prm[r*8 + 0] * wbuf[r*WSTR + j] / (kn[r] * g_mnorm[j] + EPSV);
    }
    __syncthreads();

    // ---- pointwise: 2 warps per row, 1024 elements each -------------------
    {
        int r     = wid >> 1;
        int half  = wid & 1;
        int start = half * HALF;
        float* wr = wbuf + r*WSTR;
        float g  = prm[r*8+1], s0 = prm[r*8+2], s1 = prm[r*8+3];
        float s2 = prm[r*8+4], gm = prm[r*8+5];

        // max over own half
        float mx = -1e30f;
        #pragma unroll 4
        for (int u = 0; u < 32; u++) mx = fmaxf(mx, wr[start + lane + 32*u]);
        #pragma unroll
        for (int o = 16; o > 0; o >>= 1) mx = fmaxf(mx, __shfl_xor_sync(0xffffffffu, mx, o));
        if (lane == 0) red[wid] = mx;
        __syncthreads();
        mx = fmaxf(red[r*2], red[r*2+1]);

        // exp + sum over own half
        float sum = 0.f;
        #pragma unroll 4
        for (int u = 0; u < 32; u++) {
            int idx = start + lane + 32*u;
            float e = fast_expf(wr[idx] - mx);
            wr[idx] = e;
            sum += e;
        }
        #pragma unroll
        for (int o = 16; o > 0; o >>= 1) sum += __shfl_xor_sync(0xffffffffu, sum, o);
        if (lane == 0) red[wid] = sum;
        __syncthreads();
        sum = red[r*2] + red[r*2+1];

        // blend over own half
        float gc = g / sum, og = 1.f - g;
        const float* wp = wprev + (size_t)(row0 + r) * NROWS;
        #pragma unroll 4
        for (int u = 0; u < 32; u++) {
            int idx = start + lane + 32*u;
            wr[idx] = gc * wr[idx] + og * __ldg(wp + idx);
        }
        __syncthreads();   // all blends visible before boundary pre-reads

        // boundary pre-reads (post-blend values from the other region)
        float lftb = wr[(start + NROWS - 1) & (NROWS - 1)];
        float rgtb = wr[(start + HALF)      & (NROWS - 1)];
        __syncthreads();   // all pre-reads done before any writes

        // shift + sharpen over own half (carry trick within region)
        float carry = lftb;
        float psum  = 0.f;
        for (int ch = 0; ch < 32; ch++) {
            int j = start + ch*32 + lane;
            float c0  = wr[j];
            float lft = (lane == 0) ? carry : wr[j-1];
            float rgt = (ch == 31 && lane == 31) ? rgtb : wr[j+1];
            float t = s0*lft + s1*c0 + s2*rgt + EPSV;
            float p = fast_powf(t, gm);
            __syncwarp();
            wr[j] = p;
            carry = __shfl_sync(0xffffffffu, c0, 31);
            psum += p;
            __syncwarp();
        }
        #pragma unroll
        for (int o = 16; o > 0; o >>= 1) psum += __shfl_xor_sync(0xffffffffu, psum, o);
        if (lane == 0) red[wid] = psum;
        __syncthreads();
        if (half == 0 && lane == 0) ips[r] = 1.f / (red[r*2] + red[r*2+1]);
    }
    __syncthreads();

    // round w (unnormalized) to tf32 in place
    for (int i = tid; i < RPB*NROWS; i += K2T) {
        int r = i >> 11, j = i & (NROWS-1);
        wbuf[r*WSTR + j] = to_tf32f(wbuf[r*WSTR + j]);
    }
    __syncthreads();

    // ---- read GEMM (wmma): out_blk = w @ M, 8 n-tiles x 4 K-quarters ------
    {
        int n0 = (wid & 7) * 16;
        int kq = wid >> 3;                     // 0..3
        FragC acc;
        wmma::fill_fragment(acc, 0.0f);
        for (int kk = 0; kk < 64; kk++) {
            int kg = kq * 512 + kk * 8;
            FragA a;
            FragBR b;
            wmma::load_matrix_sync(a, wbuf + kg, WSTR);
            wmma::load_matrix_sync(b, g_m32 + (size_t)kg * NCOLS + n0, NCOLS);
            wmma::mma_sync(acc, a, b, acc);
        }
        wmma::store_matrix_sync(scr + kq * RPB * SCRL + n0, acc, SCRL,
                                wmma::mem_row_major);
    }
    __syncthreads();
    #pragma unroll
    for (int u = 0; u < 2; u++) {
        int idx = tid + u * K2T;
        int r = idx >> 7, c = idx & 127;
        float v = scr[r*SCRL + c] + scr[RPB*SCRL + r*SCRL + c]
                + scr[2*RPB*SCRL + r*SCRL + c] + scr[3*RPB*SCRL + r*SCRL + c];
        out[(size_t)(row0 + r) * NCOLS + c] = v * ips[r];
    }
}

// ---------------- launch ----------------------------------------------------
extern "C" void kernel_launch(void* const* d_in, const int* in_sizes, int n_in,
                              void* d_out, int out_size) {
    const float *x = 0, *W = 0, *b = 0, *M = 0, *wprev = 0;
    for (int i = 0; i < n_in; i++) {
        switch (in_sizes[i]) {
            case B_SZ * CTRL:   x     = (const float*)d_in[i]; break;
            case CTRL * NH:     W     = (const float*)d_in[i]; break;
            case NH:            b     = (const float*)d_in[i]; break;
            case NROWS * NCOLS: M     = (const float*)d_in[i]; break;
            case B_SZ * NROWS:  wprev = (const float*)d_in[i]; break;
        }
    }
    float* out = (float*)d_out;

    cudaFuncSetAttribute(k1_gemm, cudaFuncAttributeMaxDynamicSharedMemorySize, K1_SMEM);
    cudaFuncSetAttribute(k2_fused, cudaFuncAttributeMaxDynamicSharedMemorySize,
                         K2_SMEM_BYTES);

    k0_mnorm<<<NROWS/8, 256>>>(M);
    k0_mrnd <<<(NROWS*NCOLS)/256, 256>>>(M);
    k1_gemm <<<B_SZ/128, 256, K1_SMEM>>>(x, W, b);
    k2_fused<<<B_SZ/RPB, K2T, K2_SMEM_BYTES>>>(wprev, out);
}

// round 15
// speedup vs baseline: 1.6852x; 1.0849x over previous
#include <cuda_runtime.h>
#include <cstdint>
#include <math.h>
#include <mma.h>

using namespace nvcuda;

#define B_SZ   16384
#define NROWS  2048
#define NCOLS  128
#define CTRL   1024
#define NH     134            // NCOLS + 6
#define EPSV   1e-16f

// ---------------- scratch (device globals) ---------------------------------
__device__ float g_k[B_SZ * NCOLS];      // controller key k  [B,128]
__device__ float g_prm[B_SZ * 6];        // beta, g, s0,s1,s2, gamma
__device__ float g_mnorm[NROWS];         // ||M_j|| (exact)
__device__ float g_m32[NROWS * NCOLS];   // M rounded to tf32 (rna)

__device__ __forceinline__ float softplusf(float x) {
    return (x > 20.f) ? x : log1pf(expf(x));
}
__device__ __forceinline__ float fast_exp2f(float y) {
    y = fminf(fmaxf(y, -125.f), 126.f);
    float r = y + 12582912.f;
    int   n = __float_as_int(r) - 0x4B400000;
    float f = y - (r - 12582912.f);
    float p = 1.54035304e-4f;
    p = fmaf(p, f, 1.33335581e-3f);
    p = fmaf(p, f, 9.61812911e-3f);
    p = fmaf(p, f, 5.55041087e-2f);
    p = fmaf(p, f, 2.40226507e-1f);
    p = fmaf(p, f, 6.93147183e-1f);
    p = fmaf(p, f, 1.0f);
    return __int_as_float(__float_as_int(p) + (n << 23));
}
__device__ __forceinline__ float fast_expf(float x) { return fast_exp2f(x * 1.442695041f); }
__device__ __forceinline__ float fast_log2f(float x) {
    int   ib = __float_as_int(x);
    int   e  = (ib - 0x3f2aaaab) & 0xff800000;
    float m  = __int_as_float(ib - e);
    float le = (float)(e >> 23);
    float f  = m - 1.0f;
    float s  = f * f;
    float r  = fmaf(0.230836749f, f, -0.279208571f);
    float t  = fmaf(0.331826031f, f, -0.498910338f);
    r = fmaf(r, s, t);
    r = fmaf(r, s, f);
    return fmaf(r, 1.442695041f, le);
}
__device__ __forceinline__ float fast_powf(float x, float g) {
    return fast_exp2f(g * fast_log2f(x));
}
__device__ __forceinline__ float to_tf32f(float x) {
    uint32_t r; asm("cvt.rna.tf32.f32 %0, %1;" : "=r"(r) : "f"(x));
    return __uint_as_float(r);
}

typedef wmma::fragment<wmma::matrix_a, 16, 16, 8, wmma::precision::tf32, wmma::row_major> FragA;
typedef wmma::fragment<wmma::matrix_b, 16, 16, 8, wmma::precision::tf32, wmma::col_major> FragBC;
typedef wmma::fragment<wmma::matrix_b, 16, 16, 8, wmma::precision::tf32, wmma::row_major> FragBR;
typedef wmma::fragment<wmma::accumulator, 16, 16, 8, float> FragC;

// ---------------- K0: M row norms (exact) + tf32 copy ----------------------
__global__ void k0_mnorm(const float* __restrict__ M) {
    int row  = blockIdx.x * 8 + (threadIdx.x >> 5);
    int lane = threadIdx.x & 31;
    float4 v = ((const float4*)(M + (size_t)row * NCOLS))[lane];
    float s = v.x*v.x + v.y*v.y + v.z*v.z + v.w*v.w;
    #pragma unroll
    for (int o = 16; o > 0; o >>= 1) s += __shfl_xor_sync(0xffffffffu, s, o);
    if (lane == 0) g_mnorm[row] = sqrtf(s);
}
__global__ void k0_mrnd(const float* __restrict__ M) {
    int idx = blockIdx.x * 256 + threadIdx.x;
    g_m32[idx] = to_tf32f(M[idx]);
}

// ---------------- K1: h = x@W + b, BM=64 (2 blocks/SM wave) ----------------
#define BM1 64
// float offsets
#define K1_AS    0        // [32][68] exact k-major (param path)
#define K1_AS32  2176     // [64][36] tf32
#define K1_BS32  4480     // [128][36] tf32
#define K1_STAGE 0        // [64][132] overlaps union post-mainloop
#define K1_PS    9088     // [32][6]
#define K1_HP    9280     // [2][64][6]
#define K1_SMEM  ((9280 + 768) * 4)

__global__ __launch_bounds__(256)
void k1_gemm(const float* __restrict__ x, const float* __restrict__ W,
             const float* __restrict__ bfc) {
    extern __shared__ float sm1f[];
    float* As    = sm1f + K1_AS;
    float* As32  = sm1f + K1_AS32;
    float* Bs32  = sm1f + K1_BS32;
    float* stage = sm1f + K1_STAGE;
    float* Ps    = sm1f + K1_PS;
    float* hp    = sm1f + K1_HP;

    int tid  = threadIdx.x;
    int wid  = tid >> 5;
    int wm   = wid >> 2, wn = wid & 3;      // 2 x 4 warps, warp tile 32x32
    int row0 = blockIdx.x * BM1;
    int mp   = tid & 63;
    int cg   = (tid >> 6) & 1;
    int kh   = tid >> 7;                    // k-half for param path

    FragC acc[2][2];
    #pragma unroll
    for (int mi = 0; mi < 2; mi++)
        #pragma unroll
        for (int ni = 0; ni < 2; ni++) wmma::fill_fragment(acc[mi][ni], 0.0f);
    float acc3[3] = {0.f, 0.f, 0.f};

    for (int kt = 0; kt < CTRL / 32; kt++) {
        #pragma unroll
        for (int u = 0; u < 2; u++) {
            int idx = tid + u * 256;
            int m = idx >> 3, c4 = idx & 7;
            float4 v = *(const float4*)(x + (size_t)(row0 + m) * CTRL + kt * 32 + c4 * 4);
            As[(c4*4+0)*68 + m] = v.x; As[(c4*4+1)*68 + m] = v.y;
            As[(c4*4+2)*68 + m] = v.z; As[(c4*4+3)*68 + m] = v.w;
            float* d = As32 + m * 36 + c4 * 4;
            d[0] = to_tf32f(v.x); d[1] = to_tf32f(v.y);
            d[2] = to_tf32f(v.z); d[3] = to_tf32f(v.w);
        }
        #pragma unroll
        for (int u = 0; u < 16; u++) {
            int id = tid + u * 256;
            int k = id >> 7, n = id & 127;
            Bs32[n * 36 + k] = to_tf32f(W[(size_t)(kt*32 + k) * NH + n]);
        }
        if (tid < 192)
            Ps[tid] = W[(size_t)(kt*32 + tid / 6) * NH + 128 + (tid % 6)];
        __syncthreads();

        #pragma unroll
        for (int ks = 0; ks < 4; ks++) {
            int k0 = ks * 8;
            FragA a[2];
            #pragma unroll
            for (int mi = 0; mi < 2; mi++)
                wmma::load_matrix_sync(a[mi], As32 + (wm*32 + mi*16) * 36 + k0, 36);
            #pragma unroll
            for (int ni = 0; ni < 2; ni++) {
                FragBC b;
                wmma::load_matrix_sync(b, Bs32 + (wn*32 + ni*16) * 36 + k0, 36);
                #pragma unroll
                for (int mi = 0; mi < 2; mi++)
                    wmma::mma_sync(acc[mi][ni], a[mi], b, acc[mi][ni]);
            }
        }
        // exact param accumulation, k-half per thread group
        #pragma unroll 8
        for (int kk = kh * 16; kk < kh * 16 + 16; kk++) {
            float xv = As[kk*68 + mp];
            #pragma unroll
            for (int c = 0; c < 3; c++)
                acc3[c] = fmaf(xv, Ps[kk*6 + cg*3 + c], acc3[c]);
        }
        __syncthreads();
    }

    #pragma unroll
    for (int mi = 0; mi < 2; mi++)
        #pragma unroll
        for (int ni = 0; ni < 2; ni++)
            wmma::store_matrix_sync(stage + (wm*32 + mi*16) * 132 + wn*32 + ni*16,
                                    acc[mi][ni], 132, wmma::mem_row_major);
    #pragma unroll
    for (int c = 0; c < 3; c++)
        hp[kh*384 + mp*6 + cg*3 + c] = acc3[c];
    __syncthreads();

    {
        int c4 = tid & 31;
        float4 bj = *(const float4*)(bfc + c4 * 4);
        #pragma unroll
        for (int u = 0; u < 8; u++) {
            int idx = tid + u * 256;
            int row = idx >> 5;
            float4 v = *(float4*)&stage[row * 132 + c4 * 4];
            v.x += bj.x; v.y += bj.y; v.z += bj.z; v.w += bj.w;
            *(float4*)(g_k + (size_t)(row0 + row) * NCOLS + c4 * 4) = v;
        }
    }
    if (tid < 64) {
        float h[6];
        #pragma unroll
        for (int c = 0; c < 6; c++)
            h[c] = hp[tid*6 + c] + hp[384 + tid*6 + c] + bfc[128 + c];
        float beta  = softplusf(h[0]);
        float g     = 1.f / (1.f + expf(-h[1]));
        float m3    = fmaxf(h[2], fmaxf(h[3], h[4]));
        float e0 = expf(h[2] - m3), e1 = expf(h[3] - m3), e2 = expf(h[4] - m3);
        float inv = 1.f / (e0 + e1 + e2);
        float gamma = 1.f + softplusf(h[5]);
        size_t gr = (size_t)(row0 + tid) * 6;
        g_prm[gr+0] = beta;  g_prm[gr+1] = g;
        g_prm[gr+2] = e0*inv; g_prm[gr+3] = e1*inv; g_prm[gr+4] = e2*inv;
        g_prm[gr+5] = gamma;
    }
}

// ---------------- K2: fused addressing + read, 1024 threads ----------------
#define RPB  16
#define K2T  1024
#define WSTR 2056     // wbuf row stride
#define KSTR 136      // ks row stride
#define SCRL 136
#define NKQ  4        // read-GEMM K quarters
// smem floats: wbuf 16*2056 | ks 16*136 | scr 4*16*136 | prm 128 | kn 16 | ips 16 | msh 2048
#define K2_SMEM_FLOATS (RPB*WSTR + RPB*KSTR + NKQ*RPB*SCRL + RPB*8 + RPB + RPB + 2048)
#define K2_SMEM_BYTES  (K2_SMEM_FLOATS * 4)

__global__ __launch_bounds__(K2T)
void k2_fused(const float* __restrict__ wprev, float* __restrict__ out) {
    extern __shared__ float smf[];
    float* wbuf = smf;                         // [16][2056]
    float* ks   = wbuf + RPB*WSTR;             // [16][136]
    float* scr  = ks + RPB*KSTR;               // [4][16][136]
    float* prm  = scr + NKQ*RPB*SCRL;          // [16][8]
    float* kn   = prm + RPB*8;                 // [16]
    float* ips  = kn + RPB;                    // [16]
    float* msh  = ips + RPB;                   // [2048] 1/||M_j||

    int tid  = threadIdx.x;
    int lane = tid & 31;
    int wid  = tid >> 5;                       // 0..31
    int row0 = blockIdx.x * RPB;

    // load k rows (threads 0..511) + params + 1/||M||
    if (tid < 512) {
        int r = tid >> 5;
        float4 v = *(const float4*)(g_k + (size_t)(row0 + r) * NCOLS + lane*4);
        *(float4*)&ks[r*KSTR + lane*4] = v;
    }
    if (tid < RPB*6) {
        int r = tid / 6, c = tid % 6;
        prm[r*8 + c] = g_prm[(size_t)(row0 + r) * 6 + c];
    }
    for (int i = tid; i < NROWS; i += K2T)
        msh[i] = 1.0f / g_mnorm[i];
    __syncthreads();

    // k norms (exact, before rounding): warps 0..15
    if (wid < 16) {
        float s = 0.f;
        #pragma unroll
        for (int u = 0; u < 4; u++) {
            float v = ks[wid*KSTR + lane + 32*u];
            s += v * v;
        }
        #pragma unroll
        for (int o = 16; o > 0; o >>= 1) s += __shfl_xor_sync(0xffffffffu, s, o);
        if (lane == 0) kn[wid] = sqrtf(s);
    }
    __syncthreads();

    // round ks to tf32 in place
    for (int i = tid; i < RPB*NCOLS; i += K2T) {
        int r = i >> 7, c = i & 127;
        ks[r*KSTR + c] = to_tf32f(ks[r*KSTR + c]);
    }
    __syncthreads();

    // ---- sim GEMM (wmma, A hoisted): 32 warps x 4 j-tiles -----------------
    {
        FragC acc[4];
        #pragma unroll
        for (int i = 0; i < 4; i++) wmma::fill_fragment(acc[i], 0.0f);
        #pragma unroll
        for (int kk = 0; kk < 16; kk++) {
            FragA a;
            wmma::load_matrix_sync(a, ks + kk*8, KSTR);
            #pragma unroll
            for (int i = 0; i < 4; i++) {
                int j0 = (wid * 4 + i) * 16;
                FragBC b;
                wmma::load_matrix_sync(b, g_m32 + (size_t)j0 * NCOLS + kk*8, NCOLS);
                wmma::mma_sync(acc[i], a, b, acc[i]);
            }
        }
        #pragma unroll
        for (int i = 0; i < 4; i++) {
            int j0 = (wid * 4 + i) * 16;
            wmma::store_matrix_sync(wbuf + j0, acc[i], WSTR, wmma::mem_row_major);
        }
    }
    __syncthreads();

    // ---- pointwise (warps 0..15, one row each): scale folded into max/exp
    if (wid < 16) {
        int r = wid;
        float* wr = wbuf + r*WSTR;
        float rs = prm[r*8+0] / kn[r];          // beta / ||k||
        float g  = prm[r*8+1], s0 = prm[r*8+2], s1 = prm[r*8+3];
        float s2 = prm[r*8+4], gm = prm[r*8+5];

        float mx = -1e30f;
        for (int u = 0; u < 64; u++) {
            int idx = lane + 32*u;
            mx = fmaxf(mx, wr[idx] * rs * msh[idx]);
        }
        #pragma unroll
        for (int o = 16; o > 0; o >>= 1) mx = fmaxf(mx, __shfl_xor_sync(0xffffffffu, mx, o));

        float sum = 0.f;
        for (int u = 0; u < 64; u++) {
            int idx = lane + 32*u;
            float e = fast_expf(wr[idx] * rs * msh[idx] - mx);
            wr[idx] = e;
            sum += e;
        }
        #pragma unroll
        for (int o = 16; o > 0; o >>= 1) sum += __shfl_xor_sync(0xffffffffu, sum, o);

        float gc = g / sum, og = 1.f - g;
        const float* wp = wprev + (size_t)(row0 + r) * NROWS;
        for (int u = 0; u < 64; u++) {
            int idx = lane + 32*u;
            wr[idx] = gc * wr[idx] + og * __ldg(wp + idx);
        }
        __syncwarp();

        float w0    = wr[0];
        float carry = wr[NROWS - 1];
        float psum  = 0.f;
        for (int ch = 0; ch < 64; ch++) {
            int j = ch*32 + lane;
            float c0  = wr[j];
            float lft = (lane == 0)      ? carry : wr[j-1];
            float rgt = (j == NROWS - 1) ? w0    : wr[j+1];
            float t = s0*lft + s1*c0 + s2*rgt + EPSV;
            float p = fast_powf(t, gm);
            __syncwarp();
            wr[j] = to_tf32f(p);                // tf32 rounding folded in
            carry = __shfl_sync(0xffffffffu, c0, 31);
            psum += p;
            __syncwarp();
        }
        #pragma unroll
        for (int o = 16; o > 0; o >>= 1) psum += __shfl_xor_sync(0xffffffffu, psum, o);
        if (lane == 0) ips[r] = 1.f / psum;
    }
    __syncthreads();

    // ---- read GEMM (wmma): out_blk = w @ M, 8 n-tiles x 4 K-quarters ------
    {
        int n0 = (wid & 7) * 16;
        int kq = wid >> 3;                     // 0..3
        FragC acc;
        wmma::fill_fragment(acc, 0.0f);
        for (int kk = 0; kk < 64; kk++) {
            int kg = kq * 512 + kk * 8;
            FragA a;
            FragBR b;
            wmma::load_matrix_sync(a, wbuf + kg, WSTR);
            wmma::load_matrix_sync(b, g_m32 + (size_t)kg * NCOLS + n0, NCOLS);
            wmma::mma_sync(acc, a, b, acc);
        }
        wmma::store_matrix_sync(scr + kq * RPB * SCRL + n0, acc, SCRL,
                                wmma::mem_row_major);
    }
    __syncthreads();
    #pragma unroll
    for (int u = 0; u < 2; u++) {
        int idx = tid + u * K2T;
        int r = idx >> 7, c = idx & 127;
        float v = scr[r*SCRL + c] + scr[RPB*SCRL + r*SCRL + c]
                + scr[2*RPB*SCRL + r*SCRL + c] + scr[3*RPB*SCRL + r*SCRL + c];
        out[(size_t)(row0 + r) * NCOLS + c] = v * ips[r];
    }
}

// ---------------- launch ----------------------------------------------------
extern "C" void kernel_launch(void* const* d_in, const int* in_sizes, int n_in,
                              void* d_out, int out_size) {
    const float *x = 0, *W = 0, *b = 0, *M = 0, *wprev = 0;
    for (int i = 0; i < n_in; i++) {
        switch (in_sizes[i]) {
            case B_SZ * CTRL:   x     = (const float*)d_in[i]; break;
            case CTRL * NH:     W     = (const float*)d_in[i]; break;
            case NH:            b     = (const float*)d_in[i]; break;
            case NROWS * NCOLS: M     = (const float*)d_in[i]; break;
            case B_SZ * NROWS:  wprev = (const float*)d_in[i]; break;
        }
    }
    float* out = (float*)d_out;

    cudaFuncSetAttribute(k1_gemm, cudaFuncAttributeMaxDynamicSharedMemorySize, K1_SMEM);
    cudaFuncSetAttribute(k2_fused, cudaFuncAttributeMaxDynamicSharedMemorySize,
                         K2_SMEM_BYTES);

    k0_mnorm<<<NROWS/8, 256>>>(M);
    k0_mrnd <<<(NROWS*NCOLS)/256, 256>>>(M);
    k1_gemm <<<B_SZ/BM1, 256, K1_SMEM>>>(x, W, b);
    k2_fused<<<B_SZ/RPB, K2T, K2_SMEM_BYTES>>>(wprev, out);
}

// round 16
// speedup vs baseline: 1.7474x; 1.0369x over previous
#include <cuda_runtime.h>
#include <cstdint>
#include <math.h>
#include <mma.h>

using namespace nvcuda;

#define B_SZ   16384
#define NROWS  2048
#define NCOLS  128
#define CTRL   1024
#define NH     134            // NCOLS + 6
#define EPSV   1e-16f

// ---------------- scratch (device globals) ---------------------------------
__device__ float g_k[B_SZ * NCOLS];      // controller key k  [B,128]
__device__ float g_prm[B_SZ * 6];        // beta, g, s0,s1,s2, gamma
__device__ float g_mnorm[NROWS];         // ||M_j|| (exact)
__device__ float g_m32[NROWS * NCOLS];   // M rounded to tf32  [j][k]
__device__ float g_mt32[NCOLS * NROWS];  // M^T rounded to tf32 [k][j]

__device__ __forceinline__ float softplusf(float x) {
    return (x > 20.f) ? x : log1pf(expf(x));
}
__device__ __forceinline__ float fast_exp2f(float y) {
    y = fminf(fmaxf(y, -125.f), 126.f);
    float r = y + 12582912.f;
    int   n = __float_as_int(r) - 0x4B400000;
    float f = y - (r - 12582912.f);
    float p = 1.54035304e-4f;
    p = fmaf(p, f, 1.33335581e-3f);
    p = fmaf(p, f, 9.61812911e-3f);
    p = fmaf(p, f, 5.55041087e-2f);
    p = fmaf(p, f, 2.40226507e-1f);
    p = fmaf(p, f, 6.93147183e-1f);
    p = fmaf(p, f, 1.0f);
    return __int_as_float(__float_as_int(p) + (n << 23));
}
__device__ __forceinline__ float fast_expf(float x) { return fast_exp2f(x * 1.442695041f); }
__device__ __forceinline__ float fast_log2f(float x) {
    int   ib = __float_as_int(x);
    int   e  = (ib - 0x3f2aaaab) & 0xff800000;
    float m  = __int_as_float(ib - e);
    float le = (float)(e >> 23);
    float f  = m - 1.0f;
    float s  = f * f;
    float r  = fmaf(0.230836749f, f, -0.279208571f);
    float t  = fmaf(0.331826031f, f, -0.498910338f);
    r = fmaf(r, s, t);
    r = fmaf(r, s, f);
    return fmaf(r, 1.442695041f, le);
}
__device__ __forceinline__ float fast_powf(float x, float g) {
    return fast_exp2f(g * fast_log2f(x));
}
__device__ __forceinline__ float to_tf32f(float x) {
    uint32_t r; asm("cvt.rna.tf32.f32 %0, %1;" : "=r"(r) : "f"(x));
    return __uint_as_float(r);
}

typedef wmma::fragment<wmma::matrix_a, 16, 16, 8, wmma::precision::tf32, wmma::row_major> FragA;
typedef wmma::fragment<wmma::matrix_b, 16, 16, 8, wmma::precision::tf32, wmma::col_major> FragBC;
typedef wmma::fragment<wmma::matrix_b, 16, 16, 8, wmma::precision::tf32, wmma::row_major> FragBR;
typedef wmma::fragment<wmma::accumulator, 16, 16, 8, float> FragC;

// ---------------- K0: M row norms (exact) + tf32 copies --------------------
__global__ void k0_mnorm(const float* __restrict__ M) {
    int row  = blockIdx.x * 8 + (threadIdx.x >> 5);
    int lane = threadIdx.x & 31;
    float4 v = ((const float4*)(M + (size_t)row * NCOLS))[lane];
    float s = v.x*v.x + v.y*v.y + v.z*v.z + v.w*v.w;
    #pragma unroll
    for (int o = 16; o > 0; o >>= 1) s += __shfl_xor_sync(0xffffffffu, s, o);
    if (lane == 0) g_mnorm[row] = sqrtf(s);
}
__global__ void k0_mrnd(const float* __restrict__ M) {
    int idx = blockIdx.x * 256 + threadIdx.x;
    g_m32[idx] = to_tf32f(M[idx]);
}
__global__ void k0_mt32(const float* __restrict__ M) {
    int idx = blockIdx.x * 256 + threadIdx.x;      // [k][j] order, j fastest
    int c = idx >> 11, j = idx & 2047;
    g_mt32[idx] = to_tf32f(__ldg(M + (size_t)j * NCOLS + c));
}

// ---------------- K1: h = x@W + b, BM=64 (R15-proven) ----------------------
#define BM1 64
#define K1_AS    0        // [32][68] exact k-major (param path)
#define K1_AS32  2176     // [64][36] tf32
#define K1_BS32  4480     // [128][36] tf32
#define K1_STAGE 0        // [64][132] overlaps union post-mainloop
#define K1_PS    9088     // [32][6]
#define K1_HP    9280     // [2][64][6]
#define K1_SMEM  ((9280 + 768) * 4)

__global__ __launch_bounds__(256)
void k1_gemm(const float* __restrict__ x, const float* __restrict__ W,
             const float* __restrict__ bfc) {
    extern __shared__ float sm1f[];
    float* As    = sm1f + K1_AS;
    float* As32  = sm1f + K1_AS32;
    float* Bs32  = sm1f + K1_BS32;
    float* stage = sm1f + K1_STAGE;
    float* Ps    = sm1f + K1_PS;
    float* hp    = sm1f + K1_HP;

    int tid  = threadIdx.x;
    int wid  = tid >> 5;
    int wm   = wid >> 2, wn = wid & 3;
    int row0 = blockIdx.x * BM1;
    int mp   = tid & 63;
    int cg   = (tid >> 6) & 1;
    int kh   = tid >> 7;

    FragC acc[2][2];
    #pragma unroll
    for (int mi = 0; mi < 2; mi++)
        #pragma unroll
        for (int ni = 0; ni < 2; ni++) wmma::fill_fragment(acc[mi][ni], 0.0f);
    float acc3[3] = {0.f, 0.f, 0.f};

    for (int kt = 0; kt < CTRL / 32; kt++) {
        #pragma unroll
        for (int u = 0; u < 2; u++) {
            int idx = tid + u * 256;
            int m = idx >> 3, c4 = idx & 7;
            float4 v = *(const float4*)(x + (size_t)(row0 + m) * CTRL + kt * 32 + c4 * 4);
            As[(c4*4+0)*68 + m] = v.x; As[(c4*4+1)*68 + m] = v.y;
            As[(c4*4+2)*68 + m] = v.z; As[(c4*4+3)*68 + m] = v.w;
            float* d = As32 + m * 36 + c4 * 4;
            d[0] = to_tf32f(v.x); d[1] = to_tf32f(v.y);
            d[2] = to_tf32f(v.z); d[3] = to_tf32f(v.w);
        }
        #pragma unroll
        for (int u = 0; u < 16; u++) {
            int id = tid + u * 256;
            int k = id >> 7, n = id & 127;
            Bs32[n * 36 + k] = to_tf32f(W[(size_t)(kt*32 + k) * NH + n]);
        }
        if (tid < 192)
            Ps[tid] = W[(size_t)(kt*32 + tid / 6) * NH + 128 + (tid % 6)];
        __syncthreads();

        #pragma unroll
        for (int ks = 0; ks < 4; ks++) {
            int k0 = ks * 8;
            FragA a[2];
            #pragma unroll
            for (int mi = 0; mi < 2; mi++)
                wmma::load_matrix_sync(a[mi], As32 + (wm*32 + mi*16) * 36 + k0, 36);
            #pragma unroll
            for (int ni = 0; ni < 2; ni++) {
                FragBC b;
                wmma::load_matrix_sync(b, Bs32 + (wn*32 + ni*16) * 36 + k0, 36);
                #pragma unroll
                for (int mi = 0; mi < 2; mi++)
                    wmma::mma_sync(acc[mi][ni], a[mi], b, acc[mi][ni]);
            }
        }
        #pragma unroll 8
        for (int kk = kh * 16; kk < kh * 16 + 16; kk++) {
            float xv = As[kk*68 + mp];
            #pragma unroll
            for (int c = 0; c < 3; c++)
                acc3[c] = fmaf(xv, Ps[kk*6 + cg*3 + c], acc3[c]);
        }
        __syncthreads();
    }

    #pragma unroll
    for (int mi = 0; mi < 2; mi++)
        #pragma unroll
        for (int ni = 0; ni < 2; ni++)
            wmma::store_matrix_sync(stage + (wm*32 + mi*16) * 132 + wn*32 + ni*16,
                                    acc[mi][ni], 132, wmma::mem_row_major);
    #pragma unroll
    for (int c = 0; c < 3; c++)
        hp[kh*384 + mp*6 + cg*3 + c] = acc3[c];
    __syncthreads();

    {
        int c4 = tid & 31;
        float4 bj = *(const float4*)(bfc + c4 * 4);
        #pragma unroll
        for (int u = 0; u < 8; u++) {
            int idx = tid + u * 256;
            int row = idx >> 5;
            float4 v = *(float4*)&stage[row * 132 + c4 * 4];
            v.x += bj.x; v.y += bj.y; v.z += bj.z; v.w += bj.w;
            *(float4*)(g_k + (size_t)(row0 + row) * NCOLS + c4 * 4) = v;
        }
    }
    if (tid < 64) {
        float h[6];
        #pragma unroll
        for (int c = 0; c < 6; c++)
            h[c] = hp[tid*6 + c] + hp[384 + tid*6 + c] + bfc[128 + c];
        float beta  = softplusf(h[0]);
        float g     = 1.f / (1.f + expf(-h[1]));
        float m3    = fmaxf(h[2], fmaxf(h[3], h[4]));
        float e0 = expf(h[2] - m3), e1 = expf(h[3] - m3), e2 = expf(h[4] - m3);
        float inv = 1.f / (e0 + e1 + e2);
        float gamma = 1.f + softplusf(h[5]);
        size_t gr = (size_t)(row0 + tid) * 6;
        g_prm[gr+0] = beta;  g_prm[gr+1] = g;
        g_prm[gr+2] = e0*inv; g_prm[gr+3] = e1*inv; g_prm[gr+4] = e2*inv;
        g_prm[gr+5] = gamma;
    }
}

// ---------------- K2: fused addressing + read, 1024 threads ----------------
#define RPB  16
#define K2T  1024
#define WSTR 2056     // wbuf row stride
#define KSTR 136      // ks row stride
#define SCRL 136
#define NKQ  4
#define KCH  64       // read-GEMM staged k-rows per outer iter
// smem floats: wbuf 16*2056 | ks 16*136 | scr(∪Bst) 4*16*136 | prm 128 | kn 16 | ips 16 | msh 2048
#define K2_SMEM_FLOATS (RPB*WSTR + RPB*KSTR + NKQ*RPB*SCRL + RPB*8 + RPB + RPB + 2048)
#define K2_SMEM_BYTES  (K2_SMEM_FLOATS * 4)

__global__ __launch_bounds__(K2T)
void k2_fused(const float* __restrict__ wprev, float* __restrict__ out) {
    extern __shared__ float smf[];
    float* wbuf = smf;                         // [16][2056]
    float* ks   = wbuf + RPB*WSTR;             // [16][136]
    float* scr  = ks + RPB*KSTR;               // [4][16][136]  (∪ Bst [64][132])
    float* prm  = scr + NKQ*RPB*SCRL;          // [16][8]
    float* kn   = prm + RPB*8;                 // [16]
    float* ips  = kn + RPB;                    // [16]
    float* msh  = ips + RPB;                   // [2048] 1/||M_j||
    float* Bst  = scr;                         // staging union

    int tid  = threadIdx.x;
    int lane = tid & 31;
    int wid  = tid >> 5;                       // 0..31
    int row0 = blockIdx.x * RPB;

    if (tid < 512) {
        int r = tid >> 5;
        float4 v = *(const float4*)(g_k + (size_t)(row0 + r) * NCOLS + lane*4);
        *(float4*)&ks[r*KSTR + lane*4] = v;
    }
    if (tid < RPB*6) {
        int r = tid / 6, c = tid % 6;
        prm[r*8 + c] = g_prm[(size_t)(row0 + r) * 6 + c];
    }
    for (int i = tid; i < NROWS; i += K2T)
        msh[i] = 1.0f / g_mnorm[i];
    __syncthreads();

    if (wid < 16) {
        float s = 0.f;
        #pragma unroll
        for (int u = 0; u < 4; u++) {
            float v = ks[wid*KSTR + lane + 32*u];
            s += v * v;
        }
        #pragma unroll
        for (int o = 16; o > 0; o >>= 1) s += __shfl_xor_sync(0xffffffffu, s, o);
        if (lane == 0) kn[wid] = sqrtf(s);
    }
    __syncthreads();

    for (int i = tid; i < RPB*NCOLS; i += K2T) {
        int r = i >> 7, c = i & 127;
        ks[r*KSTR + c] = to_tf32f(ks[r*KSTR + c]);
    }
    __syncthreads();

    // ---- sim GEMM: B = M^T (row-major frags, 64B segments) ----------------
    {
        FragC acc[4];
        #pragma unroll
        for (int i = 0; i < 4; i++) wmma::fill_fragment(acc[i], 0.0f);
        #pragma unroll
        for (int kk = 0; kk < 16; kk++) {
            FragA a;
            wmma::load_matrix_sync(a, ks + kk*8, KSTR);
            #pragma unroll
            for (int i = 0; i < 4; i++) {
                int j0 = (wid * 4 + i) * 16;
                FragBR b;    // B[k][j] = g_mt32, ldm = NROWS
                wmma::load_matrix_sync(b, g_mt32 + (size_t)(kk*8) * NROWS + j0, NROWS);
                wmma::mma_sync(acc[i], a, b, acc[i]);
            }
        }
        #pragma unroll
        for (int i = 0; i < 4; i++) {
            int j0 = (wid * 4 + i) * 16;
            wmma::store_matrix_sync(wbuf + j0, acc[i], WSTR, wmma::mem_row_major);
        }
    }
    __syncthreads();

    // ---- pointwise (warps 0..15, one row each; scale folded) --------------
    if (wid < 16) {
        int r = wid;
        float* wr = wbuf + r*WSTR;
        float rs = prm[r*8+0] / kn[r];
        float g  = prm[r*8+1], s0 = prm[r*8+2], s1 = prm[r*8+3];
        float s2 = prm[r*8+4], gm = prm[r*8+5];

        float mx = -1e30f;
        for (int u = 0; u < 64; u++) {
            int idx = lane + 32*u;
            mx = fmaxf(mx, wr[idx] * rs * msh[idx]);
        }
        #pragma unroll
        for (int o = 16; o > 0; o >>= 1) mx = fmaxf(mx, __shfl_xor_sync(0xffffffffu, mx, o));

        float sum = 0.f;
        for (int u = 0; u < 64; u++) {
            int idx = lane + 32*u;
            float e = fast_expf(wr[idx] * rs * msh[idx] - mx);
            wr[idx] = e;
            sum += e;
        }
        #pragma unroll
        for (int o = 16; o > 0; o >>= 1) sum += __shfl_xor_sync(0xffffffffu, sum, o);

        float gc = g / sum, og = 1.f - g;
        const float* wp = wprev + (size_t)(row0 + r) * NROWS;
        for (int u = 0; u < 64; u++) {
            int idx = lane + 32*u;
            wr[idx] = gc * wr[idx] + og * __ldg(wp + idx);
        }
        __syncwarp();

        float w0    = wr[0];
        float carry = wr[NROWS - 1];
        float psum  = 0.f;
        for (int ch = 0; ch < 64; ch++) {
            int j = ch*32 + lane;
            float c0  = wr[j];
            float lft = (lane == 0)      ? carry : wr[j-1];
            float rgt = (j == NROWS - 1) ? w0    : wr[j+1];
            float t = s0*lft + s1*c0 + s2*rgt + EPSV;
            float p = fast_powf(t, gm);
            __syncwarp();
            wr[j] = to_tf32f(p);
            carry = __shfl_sync(0xffffffffu, c0, 31);
            psum += p;
            __syncwarp();
        }
        #pragma unroll
        for (int o = 16; o > 0; o >>= 1) psum += __shfl_xor_sync(0xffffffffu, psum, o);
        if (lane == 0) ips[r] = 1.f / psum;
    }
    __syncthreads();

    // ---- read GEMM: out_blk = w @ M, smem-staged M chunks -----------------
    {
        int n0 = (wid & 7) * 16;
        int kq = wid >> 3;                     // 0..3
        FragC acc;
        wmma::fill_fragment(acc, 0.0f);
        for (int oc = 0; oc < NROWS / KCH; oc++) {       // 32 outer chunks
            // stage M[oc*64 .. +64][0:128] into Bst (coalesced 128B lines)
            #pragma unroll
            for (int u = 0; u < 2; u++) {
                int idx = tid + u * K2T;       // 2048 float4s
                int kr = idx >> 5, c4 = idx & 31;
                float4 v = *(const float4*)(g_m32 + (size_t)(oc*KCH + kr) * NCOLS + c4 * 4);
                *(float4*)&Bst[kr*132 + c4*4] = v;
            }
            __syncthreads();
            #pragma unroll
            for (int s = 0; s < 2; s++) {
                int kr = kq * 16 + s * 8;      // local k-row in chunk
                FragA a;
                FragBR b;
                wmma::load_matrix_sync(a, wbuf + (oc*KCH + kr), WSTR);
                wmma::load_matrix_sync(b, Bst + kr*132 + n0, 132);
                wmma::mma_sync(acc, a, b, acc);
            }
            __syncthreads();
        }
        // scr overlaps Bst; all Bst reads complete (sync above)
        wmma::store_matrix_sync(scr + kq * RPB * SCRL + n0, acc, SCRL,
                                wmma::mem_row_major);
    }
    __syncthreads();
    #pragma unroll
    for (int u = 0; u < 2; u++) {
        int idx = tid + u * K2T;
        int r = idx >> 7, c = idx & 127;
        float v = scr[r*SCRL + c] + scr[RPB*SCRL + r*SCRL + c]
                + scr[2*RPB*SCRL + r*SCRL + c] + scr[3*RPB*SCRL + r*SCRL + c];
        out[(size_t)(row0 + r) * NCOLS + c] = v * ips[r];
    }
}

// ---------------- launch ----------------------------------------------------
extern "C" void kernel_launch(void* const* d_in, const int* in_sizes, int n_in,
                              void* d_out, int out_size) {
    const float *x = 0, *W = 0, *b = 0, *M = 0, *wprev = 0;
    for (int i = 0; i < n_in; i++) {
        switch (in_sizes[i]) {
            case B_SZ * CTRL:   x     = (const float*)d_in[i]; break;
            case CTRL * NH:     W     = (const float*)d_in[i]; break;
            case NH:            b     = (const float*)d_in[i]; break;
            case NROWS * NCOLS: M     = (const float*)d_in[i]; break;
            case B_SZ * NROWS:  wprev = (const float*)d_in[i]; break;
        }
    }
    float* out = (float*)d_out;

    cudaFuncSetAttribute(k1_gemm, cudaFuncAttributeMaxDynamicSharedMemorySize, K1_SMEM);
    cudaFuncSetAttribute(k2_fused, cudaFuncAttributeMaxDynamicSharedMemorySize,
                         K2_SMEM_BYTES);

    k0_mnorm<<<NROWS/8, 256>>>(M);
    k0_mrnd <<<(NROWS*NCOLS)/256, 256>>>(M);
    k0_mt32 <<<(NROWS*NCOLS)/256, 256>>>(M);
    k1_gemm <<<B_SZ/BM1, 256, K1_SMEM>>>(x, W, b);
    k2_fused<<<B_SZ/RPB, K2T, K2_SMEM_BYTES>>>(wprev, out);
}